// round 6
// baseline (speedup 1.0000x reference)
#include <cuda_runtime.h>
#include <math.h>
#include <stdint.h>

// ---------------- problem dims ----------------
#define Bq 4
#define Sq 1024
#define Eq 1024
#define Hh 16
#define Dd 64
#define FFq 4096
#define LN_EPS 1e-5f

// ---------------- scratch (device globals) ----------------
__device__ float g_V[Bq * Sq * Eq];
__device__ float g_K[Bq * Sq * Eq];
__device__ float g_Q[Bq * Sq * Eq];
__device__ float g_Vt[Bq * Sq * Eq];
__device__ float g_ctx[Bq * Sq * Eq];
__device__ float g_ao[Bq * Sq * Eq];
__device__ float g_x[Bq * Sq * Eq];
__device__ float g_xr[Bq * Sq * Eq];
__device__ float g_h[(size_t)Bq * Sq * FFq];
__device__ float g_ff[Bq * Sq * Eq];
__device__ float g_vr[Bq * Sq * Eq];
__device__ float g_kr[Bq * Sq * Eq];
__device__ float g_qr[Bq * Sq * Eq];
__device__ float g_Wvt[Eq * Eq];
__device__ float g_Wkt[Eq * Eq];
__device__ float g_Wqt[Eq * Eq];
__device__ float g_Wot[Eq * Eq];
__device__ float g_W1t[(size_t)Eq * FFq];
__device__ float g_W2t[(size_t)Eq * FFq];

// ---------------- PTX helpers ----------------
__device__ __forceinline__ uint32_t smem_u32(const void* p) {
    uint32_t a;
    asm("{ .reg .u64 t; cvta.to.shared.u64 t, %1; cvt.u32.u64 %0, t; }" : "=r"(a) : "l"(p));
    return a;
}
__device__ __forceinline__ void cp_async16(uint32_t dst, const void* src) {
    asm volatile("cp.async.ca.shared.global [%0], [%1], 16;" :: "r"(dst), "l"(src));
}
__device__ __forceinline__ void cp_commit() { asm volatile("cp.async.commit_group;"); }
template <int N>
__device__ __forceinline__ void cp_wait() { asm volatile("cp.async.wait_group %0;" :: "n"(N)); }

__device__ __forceinline__ float tf32r(float x) {
    uint32_t u;
    asm("cvt.rna.tf32.f32 %0, %1;" : "=r"(u) : "f"(x));
    return __uint_as_float(u);
}
__device__ __forceinline__ void mma_tf32(float* c, const float* a, const float* b) {
    asm volatile(
        "mma.sync.aligned.m16n8k8.row.col.f32.tf32.tf32.f32 "
        "{%0,%1,%2,%3}, {%4,%5,%6,%7}, {%8,%9}, {%0,%1,%2,%3};"
        : "+f"(c[0]), "+f"(c[1]), "+f"(c[2]), "+f"(c[3])
        : "r"(__float_as_uint(a[0])), "r"(__float_as_uint(a[1])),
          "r"(__float_as_uint(a[2])), "r"(__float_as_uint(a[3])),
          "r"(__float_as_uint(b[0])), "r"(__float_as_uint(b[1])));
}

// ---------------- tf32 rounding pass ----------------
__global__ void __launch_bounds__(256)
round_tf32_kernel(const float* __restrict__ in, float* __restrict__ out, int n4)
{
    int i = blockIdx.x * 256 + threadIdx.x;
    if (i >= n4) return;
    float4 v = ((const float4*)in)[i];
    v.x = tf32r(v.x); v.y = tf32r(v.y); v.z = tf32r(v.z); v.w = tf32r(v.w);
    ((float4*)out)[i] = v;
}

// ---------------- W[K,N] fp32 -> Wt[N,K] tf32-rounded ----------------
__global__ void __launch_bounds__(256)
transpose_tf32_kernel(const float* __restrict__ W, float* __restrict__ Wt, int K, int N)
{
    __shared__ float t[32][33];
    const int k0 = blockIdx.y * 32, n0 = blockIdx.x * 32;
    const int tx = threadIdx.x & 31, ty = threadIdx.x >> 5;
#pragma unroll
    for (int i = 0; i < 32; i += 8)
        t[ty + i][tx] = W[(size_t)(k0 + ty + i) * N + n0 + tx];
    __syncthreads();
#pragma unroll
    for (int i = 0; i < 32; i += 8)
        Wt[(size_t)(n0 + ty + i) * K + k0 + tx] = tf32r(t[tx][ty + i]);
}

// ---------------- per-batch transpose: Vt[(b*E+c)][k] = V[(b*S+k)][c] ----------------
__global__ void __launch_bounds__(256)
vtrans_kernel(const float* __restrict__ V, float* __restrict__ Vt)
{
    __shared__ float t[32][33];
    const int b = blockIdx.z;
    const int k0 = blockIdx.x * 32, c0 = blockIdx.y * 32;
    const int tx = threadIdx.x & 31, ty = threadIdx.x >> 5;
#pragma unroll
    for (int i = 0; i < 32; i += 8)
        t[ty + i][tx] = V[(size_t)(b * Sq + k0 + ty + i) * Eq + c0 + tx];
    __syncthreads();
#pragma unroll
    for (int i = 0; i < 32; i += 8)
        Vt[(size_t)(b * Eq + c0 + ty + i) * Sq + k0 + tx] = t[tx][ty + i];
}

// ---------------- tf32 MMA GEMM, 4-stage cp.async pipeline ----------------
// CTA 128x128, kt=16, 8 warps (4Mx2N, warp tile 32x64). smem stride 20 floats
// (banks (20r+c)%32 all-distinct for the fragment pattern). One sync/iter.
#define KT 16
#define PAD2 20
#define NSTAGE 4
#define GSMEM (NSTAGE * 2 * 128 * PAD2 * 4)   // 81920 B -> 2 CTAs/SM

__global__ void __launch_bounds__(256)
gemm_tf32(const float* __restrict__ A, const float* __restrict__ Bt,
          const float* __restrict__ bias, float* __restrict__ C,
          int M, int K, int N, int relu, int round_out)
{
    extern __shared__ float sm[];
    const int tid = threadIdx.x;
    const int wid = tid >> 5, lane = tid & 31;
    const int wm = wid & 3, wn = wid >> 2;
    const int row0 = blockIdx.y * 128;
    const int col0 = blockIdx.x * 128;

    const uint32_t sbase = smem_u32(sm);
    const uint32_t STAGEB = 2u * 128 * PAD2 * 4;   // bytes per stage (A+B)

    float acc[2][8][4];
#pragma unroll
    for (int i = 0; i < 2; i++)
#pragma unroll
        for (int j = 0; j < 8; j++)
#pragma unroll
            for (int k = 0; k < 4; k++) acc[i][j][k] = 0.f;

    const int NC = K / KT;

    auto load_tile = [&](int c, int slot) {
        const float* Ag = A  + (size_t)row0 * K + c * KT;
        const float* Bg = Bt + (size_t)col0 * K + c * KT;
        const uint32_t ab = sbase + (uint32_t)slot * STAGEB;
        const uint32_t bb = ab + 128 * PAD2 * 4;
#pragma unroll
        for (int i = 0; i < 2; i++) {
            int id = tid + i * 256;
            int r = id >> 2, c4 = id & 3;
            uint32_t off = (uint32_t)(r * PAD2 + c4 * 4) * 4;
            cp_async16(ab + off, Ag + (size_t)r * K + c4 * 4);
            cp_async16(bb + off, Bg + (size_t)r * K + c4 * 4);
        }
        cp_commit();
    };

    load_tile(0, 0);
    load_tile(1, 1);
    load_tile(2, 2);

    const int fr = lane >> 2;
    const int fc = lane & 3;

    for (int c = 0; c < NC; c++) {
        if (c + 2 < NC)      cp_wait<2>();
        else if (c + 1 < NC) cp_wait<1>();
        else                 cp_wait<0>();
        __syncthreads();
        if (c + 3 < NC) load_tile(c + 3, (c + 3) & 3);

        float* Abuf = sm + (size_t)(c & 3) * 2 * 128 * PAD2;
        float* Bbuf = Abuf + 128 * PAD2;

#pragma unroll
        for (int ks = 0; ks < 2; ks++) {
            const int ck = ks * 8;
            float afr[2][4], bfr[8][2];
#pragma unroll
            for (int mi = 0; mi < 2; mi++) {
                int base = (wm * 32 + mi * 16 + fr) * PAD2 + ck + fc;
                afr[mi][0] = Abuf[base];
                afr[mi][1] = Abuf[base + 8 * PAD2];
                afr[mi][2] = Abuf[base + 4];
                afr[mi][3] = Abuf[base + 8 * PAD2 + 4];
            }
#pragma unroll
            for (int ni = 0; ni < 8; ni++) {
                int base = (wn * 64 + ni * 8 + fr) * PAD2 + ck + fc;
                bfr[ni][0] = Bbuf[base];
                bfr[ni][1] = Bbuf[base + 4];
            }
#pragma unroll
            for (int mi = 0; mi < 2; mi++)
#pragma unroll
                for (int ni = 0; ni < 8; ni++)
                    mma_tf32(acc[mi][ni], afr[mi], bfr[ni]);
        }
    }

    const int qr = lane >> 2;
    const int qc = (lane & 3) * 2;
#pragma unroll
    for (int mi = 0; mi < 2; mi++) {
#pragma unroll
        for (int ni = 0; ni < 8; ni++) {
            int col = col0 + wn * 64 + ni * 8 + qc;
            float b0 = bias[col], b1 = bias[col + 1];
            int r0 = row0 + wm * 32 + mi * 16 + qr;
            float v0 = acc[mi][ni][0] + b0;
            float v1 = acc[mi][ni][1] + b1;
            float v2 = acc[mi][ni][2] + b0;
            float v3 = acc[mi][ni][3] + b1;
            if (relu) {
                v0 = fmaxf(v0, 0.f); v1 = fmaxf(v1, 0.f);
                v2 = fmaxf(v2, 0.f); v3 = fmaxf(v3, 0.f);
            }
            if (round_out) {
                v0 = tf32r(v0); v1 = tf32r(v1);
                v2 = tf32r(v2); v3 = tf32r(v3);
            }
            *(float2*)(C + (size_t)r0 * N + col)       = make_float2(v0, v1);
            *(float2*)(C + (size_t)(r0 + 8) * N + col) = make_float2(v2, v3);
        }
    }
}

// ---------------- fused flash attention, double-buffered K/V ----------------
#define QT 64
#define KTL 128
#define QS 68
#define VS 132
// Q(64*QS) + 2*K(128*QS) + 2*V(64*VS) + P(64*VS) + 256
#define FSMEM ((QT*QS + 2*KTL*QS + 2*64*VS + QT*VS + 256) * 4)   // 189440 B

__global__ void __launch_bounds__(256)
flash_kernel(const float* __restrict__ Qg, const float* __restrict__ Kg,
             const float* __restrict__ Vtg, const int* __restrict__ mask,
             float* __restrict__ ctx)
{
    extern __shared__ float sf[];
    float* Qs  = sf;                       // 64 x QS
    float* Ks  = Qs + QT * QS;             // 2 x 128 x QS
    float* Vts = Ks + 2 * KTL * QS;        // 2 x 64 x VS
    float* Ps  = Vts + 2 * 64 * VS;        // 64 x VS
    float* tmpM = Ps + QT * VS;            // 128
    float* tmpS = tmpM + 128;              // 128

    const int tid = threadIdx.x;
    const int wid = tid >> 5, lane = tid & 31;
    const int wm = wid & 3, wn = wid >> 2;
    const int qr = lane >> 2, qc = lane & 3;
    const int bh = blockIdx.y, b = bh >> 4, h = bh & 15;
    const int q0 = blockIdx.x * QT;

    const uint32_t qs_u = smem_u32(Qs), ks_u = smem_u32(Ks), vs_u = smem_u32(Vts);

    auto load_kv = [&](int kt, int buf) {
        const uint32_t kb = ks_u + (uint32_t)buf * KTL * QS * 4;
        const uint32_t vb = vs_u + (uint32_t)buf * 64 * VS * 4;
#pragma unroll
        for (int i = 0; i < 8; i++) {
            int id = tid + i * 256;
            int r = id >> 4, ch = id & 15;
            cp_async16(kb + (uint32_t)(r * QS + ch * 4) * 4,
                       Kg + (size_t)(b * Sq + kt * KTL + r) * Eq + h * 64 + ch * 4);
        }
#pragma unroll
        for (int i = 0; i < 8; i++) {
            int id = tid + i * 256;
            int r = id >> 5, ch = id & 31;
            cp_async16(vb + (uint32_t)(r * VS + ch * 4) * 4,
                       Vtg + (size_t)(b * Eq + h * 64 + r) * Sq + kt * KTL + ch * 4);
        }
        cp_commit();
    };

    // prologue: Q tile + first K/V tile
#pragma unroll
    for (int i = 0; i < 4; i++) {
        int id = tid + i * 256;
        int r = id >> 4, ch = id & 15;
        cp_async16(qs_u + (uint32_t)(r * QS + ch * 4) * 4,
                   Qg + (size_t)(b * Sq + q0 + r) * Eq + h * 64 + ch * 4);
    }
    cp_commit();
    load_kv(0, 0);

    float m0 = -INFINITY, m1 = -INFINITY;
    float l0 = 0.f, l1 = 0.f;
    float acc_o[4][4] = {};

    const int rloc = wm * 16 + qr;
    const int NT = Sq / KTL;

    for (int kt = 0; kt < NT; kt++) {
        const int buf = kt & 1;
        if (kt + 1 < NT) cp_wait<1>(); else cp_wait<0>();
        __syncthreads();
        if (kt + 1 < NT) load_kv(kt + 1, buf ^ 1);

        float* Kb = Ks + (size_t)buf * KTL * QS;
        float* Vb = Vts + (size_t)buf * 64 * VS;

        // S = Q @ K^T
        float acc_s[8][4];
#pragma unroll
        for (int ni = 0; ni < 8; ni++)
#pragma unroll
            for (int k = 0; k < 4; k++) acc_s[ni][k] = 0.f;
#pragma unroll
        for (int ks = 0; ks < 8; ks++) {
            float a[4];
            int ab = rloc * QS + ks * 8 + qc;
            a[0] = Qs[ab]; a[1] = Qs[ab + 8 * QS]; a[2] = Qs[ab + 4]; a[3] = Qs[ab + 8 * QS + 4];
#pragma unroll
            for (int ni = 0; ni < 8; ni++) {
                int bb = (wn * 64 + ni * 8 + qr) * QS + ks * 8 + qc;
                float bf[2] = { Kb[bb], Kb[bb + 4] };
                mma_tf32(acc_s[ni], a, bf);
            }
        }

        // mask + rsqrt, row max
        float mr0 = -INFINITY, mr1 = -INFINITY;
#pragma unroll
        for (int ni = 0; ni < 8; ni++) {
            int colg = kt * KTL + wn * 64 + ni * 8 + qc * 2;
            int mk0 = mask[b * Sq + colg], mk1 = mask[b * Sq + colg + 1];
            float s0 = mk0 ? rsqrtf(acc_s[ni][0]) : -INFINITY;
            float s1 = mk1 ? rsqrtf(acc_s[ni][1]) : -INFINITY;
            float s2 = mk0 ? rsqrtf(acc_s[ni][2]) : -INFINITY;
            float s3 = mk1 ? rsqrtf(acc_s[ni][3]) : -INFINITY;
            acc_s[ni][0] = s0; acc_s[ni][1] = s1; acc_s[ni][2] = s2; acc_s[ni][3] = s3;
            mr0 = fmaxf(mr0, fmaxf(s0, s1));
            mr1 = fmaxf(mr1, fmaxf(s2, s3));
        }
#pragma unroll
        for (int o = 1; o < 4; o <<= 1) {
            mr0 = fmaxf(mr0, __shfl_xor_sync(0xffffffffu, mr0, o));
            mr1 = fmaxf(mr1, __shfl_xor_sync(0xffffffffu, mr1, o));
        }
        if (qc == 0) { tmpM[wn * 64 + rloc] = mr0; tmpM[wn * 64 + rloc + 8] = mr1; }
        __syncthreads();
        float mt0 = fmaxf(tmpM[rloc],     tmpM[64 + rloc]);
        float mt1 = fmaxf(tmpM[rloc + 8], tmpM[64 + rloc + 8]);
        float mn0 = fmaxf(m0, mt0), mn1 = fmaxf(m1, mt1);
        float mn0s = (mn0 == -INFINITY) ? 0.f : mn0;
        float mn1s = (mn1 == -INFINITY) ? 0.f : mn1;
        float sc0 = __expf(m0 - mn0s);
        float sc1 = __expf(m1 - mn1s);
        m0 = mn0; m1 = mn1;

        // exp, row sum, store P (tf32-rounded)
        float sr0 = 0.f, sr1 = 0.f;
#pragma unroll
        for (int ni = 0; ni < 8; ni++) {
            float p0 = __expf(acc_s[ni][0] - mn0s);
            float p1 = __expf(acc_s[ni][1] - mn0s);
            float p2 = __expf(acc_s[ni][2] - mn1s);
            float p3 = __expf(acc_s[ni][3] - mn1s);
            sr0 += p0 + p1; sr1 += p2 + p3;
            int colp = wn * 64 + ni * 8 + qc * 2;
            Ps[rloc * VS + colp]           = tf32r(p0);
            Ps[rloc * VS + colp + 1]       = tf32r(p1);
            Ps[(rloc + 8) * VS + colp]     = tf32r(p2);
            Ps[(rloc + 8) * VS + colp + 1] = tf32r(p3);
        }
#pragma unroll
        for (int o = 1; o < 4; o <<= 1) {
            sr0 += __shfl_xor_sync(0xffffffffu, sr0, o);
            sr1 += __shfl_xor_sync(0xffffffffu, sr1, o);
        }
        if (qc == 0) { tmpS[wn * 64 + rloc] = sr0; tmpS[wn * 64 + rloc + 8] = sr1; }
        __syncthreads();
        l0 = l0 * sc0 + tmpS[rloc]     + tmpS[64 + rloc];
        l1 = l1 * sc1 + tmpS[rloc + 8] + tmpS[64 + rloc + 8];

        // rescale O
#pragma unroll
        for (int ni = 0; ni < 4; ni++) {
            acc_o[ni][0] *= sc0; acc_o[ni][1] *= sc0;
            acc_o[ni][2] *= sc1; acc_o[ni][3] *= sc1;
        }

        // O += P @ V
#pragma unroll
        for (int ks = 0; ks < 16; ks++) {
            float a[4];
            int ab = rloc * VS + ks * 8 + qc;
            a[0] = Ps[ab]; a[1] = Ps[ab + 8 * VS]; a[2] = Ps[ab + 4]; a[3] = Ps[ab + 8 * VS + 4];
#pragma unroll
            for (int ni = 0; ni < 4; ni++) {
                int bb = (wn * 32 + ni * 8 + qr) * VS + ks * 8 + qc;
                float bf[2] = { Vb[bb], Vb[bb + 4] };
                mma_tf32(acc_o[ni], a, bf);
            }
        }
    }

    // epilogue
    float inv0 = 1.f / l0, inv1 = 1.f / l1;
#pragma unroll
    for (int ni = 0; ni < 4; ni++) {
        int col = h * 64 + wn * 32 + ni * 8 + qc * 2;
        size_t r = (size_t)(b * Sq + q0 + rloc);
        *(float2*)(ctx + r * Eq + col) =
            make_float2(tf32r(acc_o[ni][0] * inv0), tf32r(acc_o[ni][1] * inv0));
        *(float2*)(ctx + (r + 8) * Eq + col) =
            make_float2(tf32r(acc_o[ni][2] * inv1), tf32r(acc_o[ni][3] * inv1));
    }
}

// ---------------- out = LayerNorm(A + R); optional tf32-rounded copy ----------------
__global__ void __launch_bounds__(256)
add_ln_kernel(const float* __restrict__ A, const float* __restrict__ R,
              const float* __restrict__ g, const float* __restrict__ be,
              float* __restrict__ out, float* __restrict__ out_r)
{
    const size_t row = blockIdx.x;
    const int tid = threadIdx.x;
    const int lane = tid & 31, warp = tid >> 5;
    __shared__ float red[8];
    const float* pa = A + row * Eq;
    const float* pr = R + row * Eq;

    float v[4];
    float s = 0.f;
#pragma unroll
    for (int i = 0; i < 4; i++) {
        v[i] = pa[tid + i * 256] + pr[tid + i * 256];
        s += v[i];
    }
#pragma unroll
    for (int o = 16; o; o >>= 1) s += __shfl_xor_sync(0xffffffffu, s, o);
    if (lane == 0) red[warp] = s;
    __syncthreads();
    if (tid == 0) {
        float t = 0.f;
#pragma unroll
        for (int i = 0; i < 8; i++) t += red[i];
        red[0] = t;
    }
    __syncthreads();
    const float mean = red[0] * (1.f / Eq);
    __syncthreads();

    float s2 = 0.f;
#pragma unroll
    for (int i = 0; i < 4; i++) {
        float d = v[i] - mean;
        s2 += d * d;
    }
#pragma unroll
    for (int o = 16; o; o >>= 1) s2 += __shfl_xor_sync(0xffffffffu, s2, o);
    if (lane == 0) red[warp] = s2;
    __syncthreads();
    if (tid == 0) {
        float t = 0.f;
#pragma unroll
        for (int i = 0; i < 8; i++) t += red[i];
        red[0] = t;
    }
    __syncthreads();
    const float inv = rsqrtf(red[0] * (1.f / Eq) + LN_EPS);

#pragma unroll
    for (int i = 0; i < 4; i++) {
        int c = tid + i * 256;
        float o = (v[i] - mean) * inv * g[c] + be[c];
        out[row * Eq + c] = o;
        if (out_r) out_r[row * Eq + c] = tf32r(o);
    }
}

// ---------------- host launch ----------------
extern "C" void kernel_launch(void* const* d_in, const int* in_sizes, int n_in,
                              void* d_out, int out_size)
{
    const float* value = (const float*)d_in[0];
    const float* key   = (const float*)d_in[1];
    const float* query = (const float*)d_in[2];
    const int*   mask  = (const int*)d_in[3];
    const float* Wv = (const float*)d_in[4];
    const float* bv = (const float*)d_in[5];
    const float* Wk = (const float*)d_in[6];
    const float* bk = (const float*)d_in[7];
    const float* Wq = (const float*)d_in[8];
    const float* bq = (const float*)d_in[9];
    const float* Wo = (const float*)d_in[10];
    const float* bo = (const float*)d_in[11];
    const float* W1 = (const float*)d_in[12];
    const float* b1 = (const float*)d_in[13];
    const float* W2 = (const float*)d_in[14];
    const float* b2 = (const float*)d_in[15];
    const float* g1  = (const float*)d_in[16];
    const float* be1 = (const float*)d_in[17];
    const float* g2  = (const float*)d_in[18];
    const float* be2 = (const float*)d_in[19];
    float* out = (float*)d_out;

    float *pV, *pK, *pQ, *pVt, *pCtx, *pAo, *pX, *pXr, *pH, *pFf;
    float *pVr, *pKr, *pQr;
    float *pWvt, *pWkt, *pWqt, *pWot, *pW1t, *pW2t;
    cudaGetSymbolAddress((void**)&pV,   g_V);
    cudaGetSymbolAddress((void**)&pK,   g_K);
    cudaGetSymbolAddress((void**)&pQ,   g_Q);
    cudaGetSymbolAddress((void**)&pVt,  g_Vt);
    cudaGetSymbolAddress((void**)&pCtx, g_ctx);
    cudaGetSymbolAddress((void**)&pAo,  g_ao);
    cudaGetSymbolAddress((void**)&pX,   g_x);
    cudaGetSymbolAddress((void**)&pXr,  g_xr);
    cudaGetSymbolAddress((void**)&pH,   g_h);
    cudaGetSymbolAddress((void**)&pFf,  g_ff);
    cudaGetSymbolAddress((void**)&pVr,  g_vr);
    cudaGetSymbolAddress((void**)&pKr,  g_kr);
    cudaGetSymbolAddress((void**)&pQr,  g_qr);
    cudaGetSymbolAddress((void**)&pWvt, g_Wvt);
    cudaGetSymbolAddress((void**)&pWkt, g_Wkt);
    cudaGetSymbolAddress((void**)&pWqt, g_Wqt);
    cudaGetSymbolAddress((void**)&pWot, g_Wot);
    cudaGetSymbolAddress((void**)&pW1t, g_W1t);
    cudaGetSymbolAddress((void**)&pW2t, g_W2t);

    cudaFuncSetAttribute(gemm_tf32, cudaFuncAttributeMaxDynamicSharedMemorySize, GSMEM);
    cudaFuncSetAttribute(flash_kernel, cudaFuncAttributeMaxDynamicSharedMemorySize, FSMEM);

    const int M = Bq * Sq;  // 4096
    dim3 blk(256);

    // weight transpose + tf32 rounding
    transpose_tf32_kernel<<<dim3(Eq / 32, Eq / 32), blk>>>(Wv, pWvt, Eq, Eq);
    transpose_tf32_kernel<<<dim3(Eq / 32, Eq / 32), blk>>>(Wk, pWkt, Eq, Eq);
    transpose_tf32_kernel<<<dim3(Eq / 32, Eq / 32), blk>>>(Wq, pWqt, Eq, Eq);
    transpose_tf32_kernel<<<dim3(Eq / 32, Eq / 32), blk>>>(Wo, pWot, Eq, Eq);
    transpose_tf32_kernel<<<dim3(FFq / 32, Eq / 32), blk>>>(W1, pW1t, Eq, FFq);
    transpose_tf32_kernel<<<dim3(Eq / 32, FFq / 32), blk>>>(W2, pW2t, FFq, Eq);

    // round activations feeding QKV GEMMs
    {
        int n4 = M * Eq / 4;
        round_tf32_kernel<<<(n4 + 255) / 256, 256>>>(value, pVr, n4);
        round_tf32_kernel<<<(n4 + 255) / 256, 256>>>(key,   pKr, n4);
        round_tf32_kernel<<<(n4 + 255) / 256, 256>>>(query, pQr, n4);
    }

    // QKV projections (tf32 MMA), outputs tf32-rounded for attention
    dim3 grid_e(Eq / 128, M / 128);
    gemm_tf32<<<grid_e, blk, GSMEM>>>(pVr, pWvt, bv, pV, M, Eq, Eq, 0, 1);
    gemm_tf32<<<grid_e, blk, GSMEM>>>(pKr, pWkt, bk, pK, M, Eq, Eq, 0, 1);
    gemm_tf32<<<grid_e, blk, GSMEM>>>(pQr, pWqt, bq, pQ, M, Eq, Eq, 0, 1);

    // V transpose per batch
    vtrans_kernel<<<dim3(Sq / 32, Eq / 32, Bq), blk>>>(pV, pVt);

    // fused flash attention -> ctx (tf32-rounded)
    flash_kernel<<<dim3(Sq / QT, Bq * Hh), blk, FSMEM>>>(pQ, pK, pVt, mask, pCtx);

    // output projection
    gemm_tf32<<<grid_e, blk, GSMEM>>>(pCtx, pWot, bo, pAo, M, Eq, Eq, 0, 0);

    // x = LN(attn_out + query); tf32-rounded copy for FFN1
    add_ln_kernel<<<M, blk>>>(pAo, query, g1, be1, pX, pXr);

    // FFN1
    dim3 grid_ff1(FFq / 128, M / 128);
    gemm_tf32<<<grid_ff1, blk, GSMEM>>>(pXr, pW1t, b1, pH, M, Eq, FFq, 1, 1);

    // FFN2
    dim3 grid_ff2(Eq / 128, M / 128);
    gemm_tf32<<<grid_ff2, blk, GSMEM>>>(pH, pW2t, b2, pFf, M, FFq, Eq, 0, 0);

    // out = LN(ff + x)
    add_ln_kernel<<<M, blk>>>(pFf, pX, g2, be2, out, nullptr);
}

// round 7
// speedup vs baseline: 1.2547x; 1.2547x over previous
#include <cuda_runtime.h>
#include <math.h>
#include <stdint.h>

// ---------------- problem dims ----------------
#define Bq 4
#define Sq 1024
#define Eq 1024
#define Hh 16
#define Dd 64
#define FFq 4096
#define LN_EPS 1e-5f

// ---------------- scratch (device globals) ----------------
__device__ float g_V[Bq * Sq * Eq];
__device__ float g_K[Bq * Sq * Eq];
__device__ float g_Q[Bq * Sq * Eq];
__device__ float g_Vt[Bq * Sq * Eq];
__device__ float g_ctx[Bq * Sq * Eq];
__device__ float g_ao[Bq * Sq * Eq];
__device__ float g_x[Bq * Sq * Eq];
__device__ float g_xr[Bq * Sq * Eq];
__device__ float g_h[(size_t)Bq * Sq * FFq];
__device__ float g_ff[Bq * Sq * Eq];
__device__ float g_vr[Bq * Sq * Eq];
__device__ float g_kr[Bq * Sq * Eq];
__device__ float g_qr[Bq * Sq * Eq];
__device__ float g_Wvt[Eq * Eq];
__device__ float g_Wkt[Eq * Eq];
__device__ float g_Wqt[Eq * Eq];
__device__ float g_Wot[Eq * Eq];
__device__ float g_W1t[(size_t)Eq * FFq];
__device__ float g_W2t[(size_t)Eq * FFq];

// ---------------- PTX helpers ----------------
__device__ __forceinline__ uint32_t smem_u32(const void* p) {
    uint32_t a;
    asm("{ .reg .u64 t; cvta.to.shared.u64 t, %1; cvt.u32.u64 %0, t; }" : "=r"(a) : "l"(p));
    return a;
}
__device__ __forceinline__ void cp_async16(uint32_t dst, const void* src) {
    asm volatile("cp.async.ca.shared.global [%0], [%1], 16;" :: "r"(dst), "l"(src));
}
__device__ __forceinline__ void cp_commit() { asm volatile("cp.async.commit_group;"); }
template <int N>
__device__ __forceinline__ void cp_wait() { asm volatile("cp.async.wait_group %0;" :: "n"(N)); }

__device__ __forceinline__ float tf32r(float x) {
    uint32_t u;
    asm("cvt.rna.tf32.f32 %0, %1;" : "=r"(u) : "f"(x));
    return __uint_as_float(u);
}
__device__ __forceinline__ void mma_tf32(float* c, const float* a, const float* b) {
    asm volatile(
        "mma.sync.aligned.m16n8k8.row.col.f32.tf32.tf32.f32 "
        "{%0,%1,%2,%3}, {%4,%5,%6,%7}, {%8,%9}, {%0,%1,%2,%3};"
        : "+f"(c[0]), "+f"(c[1]), "+f"(c[2]), "+f"(c[3])
        : "r"(__float_as_uint(a[0])), "r"(__float_as_uint(a[1])),
          "r"(__float_as_uint(a[2])), "r"(__float_as_uint(a[3])),
          "r"(__float_as_uint(b[0])), "r"(__float_as_uint(b[1])));
}

// ---------------- tf32 rounding pass ----------------
__global__ void __launch_bounds__(256)
round_tf32_kernel(const float* __restrict__ in, float* __restrict__ out, int n4)
{
    int i = blockIdx.x * 256 + threadIdx.x;
    if (i >= n4) return;
    float4 v = ((const float4*)in)[i];
    v.x = tf32r(v.x); v.y = tf32r(v.y); v.z = tf32r(v.z); v.w = tf32r(v.w);
    ((float4*)out)[i] = v;
}

// ---------------- W[K,N] fp32 -> Wt[N,K] tf32-rounded ----------------
__global__ void __launch_bounds__(256)
transpose_tf32_kernel(const float* __restrict__ W, float* __restrict__ Wt, int K, int N)
{
    __shared__ float t[32][33];
    const int k0 = blockIdx.y * 32, n0 = blockIdx.x * 32;
    const int tx = threadIdx.x & 31, ty = threadIdx.x >> 5;
#pragma unroll
    for (int i = 0; i < 32; i += 8)
        t[ty + i][tx] = W[(size_t)(k0 + ty + i) * N + n0 + tx];
    __syncthreads();
#pragma unroll
    for (int i = 0; i < 32; i += 8)
        Wt[(size_t)(n0 + ty + i) * K + k0 + tx] = tf32r(t[tx][ty + i]);
}

// ---------------- per-batch transpose: Vt[(b*E+c)][k] = V[(b*S+k)][c] ----------------
__global__ void __launch_bounds__(256)
vtrans_kernel(const float* __restrict__ V, float* __restrict__ Vt)
{
    __shared__ float t[32][33];
    const int b = blockIdx.z;
    const int k0 = blockIdx.x * 32, c0 = blockIdx.y * 32;
    const int tx = threadIdx.x & 31, ty = threadIdx.x >> 5;
#pragma unroll
    for (int i = 0; i < 32; i += 8)
        t[ty + i][tx] = V[(size_t)(b * Sq + k0 + ty + i) * Eq + c0 + tx];
    __syncthreads();
#pragma unroll
    for (int i = 0; i < 32; i += 8)
        Vt[(size_t)(b * Eq + c0 + ty + i) * Sq + k0 + tx] = t[tx][ty + i];
}

// ---------------- tf32 MMA GEMM (R5 version, known-good) ----------------
#define KT 32
#define PAD 36
#define GSMEM (2 * 2 * 128 * PAD * 4)   // 73728 B

__global__ void __launch_bounds__(256)
gemm_tf32(const float* __restrict__ A, const float* __restrict__ Bt,
          const float* __restrict__ bias, float* __restrict__ C,
          int M, int K, int N, int relu, int round_out)
{
    extern __shared__ float sm[];
    const int tid = threadIdx.x;
    const int wid = tid >> 5, lane = tid & 31;
    const int wm = wid & 3, wn = wid >> 2;
    const int row0 = blockIdx.y * 128;
    const int col0 = blockIdx.x * 128;

    const uint32_t sbase = smem_u32(sm);
    const uint32_t MATB = 128 * PAD * 4;

    float acc[2][8][4];
#pragma unroll
    for (int i = 0; i < 2; i++)
#pragma unroll
        for (int j = 0; j < 8; j++)
#pragma unroll
            for (int k = 0; k < 4; k++) acc[i][j][k] = 0.f;

    const int NC = K / KT;

    auto load_tile = [&](int c, int buf) {
        const float* Ag = A  + (size_t)row0 * K + c * KT;
        const float* Bg = Bt + (size_t)col0 * K + c * KT;
        const uint32_t ab = sbase + (uint32_t)buf * 2 * MATB;
        const uint32_t bb = ab + MATB;
#pragma unroll
        for (int i = 0; i < 4; i++) {
            int id = tid + i * 256;
            int r = id >> 3, c4 = id & 7;
            uint32_t off = (uint32_t)(r * PAD + c4 * 4) * 4;
            cp_async16(ab + off, Ag + (size_t)r * K + c4 * 4);
            cp_async16(bb + off, Bg + (size_t)r * K + c4 * 4);
        }
        cp_commit();
    };

    load_tile(0, 0);

    const int fr = lane >> 2;
    const int fc = lane & 3;

    for (int c = 0; c < NC; c++) {
        const int buf = c & 1;
        if (c + 1 < NC) { load_tile(c + 1, buf ^ 1); cp_wait<1>(); }
        else            { cp_wait<0>(); }
        __syncthreads();

        float* Abuf = sm + (size_t)buf * 2 * 128 * PAD;
        float* Bbuf = Abuf + 128 * PAD;

#pragma unroll
        for (int ks = 0; ks < 4; ks++) {
            const int ck = ks * 8;
            float afr[2][4], bfr[8][2];
#pragma unroll
            for (int mi = 0; mi < 2; mi++) {
                int base = (wm * 32 + mi * 16 + fr) * PAD + ck + fc;
                afr[mi][0] = Abuf[base];
                afr[mi][1] = Abuf[base + 8 * PAD];
                afr[mi][2] = Abuf[base + 4];
                afr[mi][3] = Abuf[base + 8 * PAD + 4];
            }
#pragma unroll
            for (int ni = 0; ni < 8; ni++) {
                int base = (wn * 64 + ni * 8 + fr) * PAD + ck + fc;
                bfr[ni][0] = Bbuf[base];
                bfr[ni][1] = Bbuf[base + 4];
            }
#pragma unroll
            for (int mi = 0; mi < 2; mi++)
#pragma unroll
                for (int ni = 0; ni < 8; ni++)
                    mma_tf32(acc[mi][ni], afr[mi], bfr[ni]);
        }
        __syncthreads();
    }

    const int qr = lane >> 2;
    const int qc = (lane & 3) * 2;
#pragma unroll
    for (int mi = 0; mi < 2; mi++) {
#pragma unroll
        for (int ni = 0; ni < 8; ni++) {
            int col = col0 + wn * 64 + ni * 8 + qc;
            float b0 = bias[col], b1 = bias[col + 1];
            int r0 = row0 + wm * 32 + mi * 16 + qr;
            float v0 = acc[mi][ni][0] + b0;
            float v1 = acc[mi][ni][1] + b1;
            float v2 = acc[mi][ni][2] + b0;
            float v3 = acc[mi][ni][3] + b1;
            if (relu) {
                v0 = fmaxf(v0, 0.f); v1 = fmaxf(v1, 0.f);
                v2 = fmaxf(v2, 0.f); v3 = fmaxf(v3, 0.f);
            }
            if (round_out) {
                v0 = tf32r(v0); v1 = tf32r(v1);
                v2 = tf32r(v2); v3 = tf32r(v3);
            }
            *(float2*)(C + (size_t)r0 * N + col)       = make_float2(v0, v1);
            *(float2*)(C + (size_t)(r0 + 8) * N + col) = make_float2(v2, v3);
        }
    }
}

// ---------------- fused flash attention, double-buffered K/V (fixed groups) ----------------
#define QT 64
#define KTL 128
#define QS 68
#define VS 132
#define FSMEM ((QT*QS + 2*KTL*QS + 2*64*VS + QT*VS + 256) * 4)   // 189440 B

__global__ void __launch_bounds__(256)
flash_kernel(const float* __restrict__ Qg, const float* __restrict__ Kg,
             const float* __restrict__ Vtg, const int* __restrict__ mask,
             float* __restrict__ ctx)
{
    extern __shared__ float sf[];
    float* Qs  = sf;                       // 64 x QS
    float* Ks  = Qs + QT * QS;             // 2 x 128 x QS
    float* Vts = Ks + 2 * KTL * QS;        // 2 x 64 x VS
    float* Ps  = Vts + 2 * 64 * VS;        // 64 x VS
    float* tmpM = Ps + QT * VS;            // 128
    float* tmpS = tmpM + 128;              // 128

    const int tid = threadIdx.x;
    const int wid = tid >> 5, lane = tid & 31;
    const int wm = wid & 3, wn = wid >> 2;
    const int qr = lane >> 2, qc = lane & 3;
    const int bh = blockIdx.y, b = bh >> 4, h = bh & 15;
    const int q0 = blockIdx.x * QT;

    const uint32_t qs_u = smem_u32(Qs), ks_u = smem_u32(Ks), vs_u = smem_u32(Vts);

    auto load_kv = [&](int kt, int buf) {
        const uint32_t kb = ks_u + (uint32_t)buf * KTL * QS * 4;
        const uint32_t vb = vs_u + (uint32_t)buf * 64 * VS * 4;
#pragma unroll
        for (int i = 0; i < 8; i++) {
            int id = tid + i * 256;
            int r = id >> 4, ch = id & 15;
            cp_async16(kb + (uint32_t)(r * QS + ch * 4) * 4,
                       Kg + (size_t)(b * Sq + kt * KTL + r) * Eq + h * 64 + ch * 4);
        }
#pragma unroll
        for (int i = 0; i < 8; i++) {
            int id = tid + i * 256;
            int r = id >> 5, ch = id & 31;
            cp_async16(vb + (uint32_t)(r * VS + ch * 4) * 4,
                       Vtg + (size_t)(b * Eq + h * 64 + r) * Sq + kt * KTL + ch * 4);
        }
        cp_commit();
    };

    // prologue: Q tile + first K/V tile (single group in flight at loop top)
#pragma unroll
    for (int i = 0; i < 4; i++) {
        int id = tid + i * 256;
        int r = id >> 4, ch = id & 15;
        cp_async16(qs_u + (uint32_t)(r * QS + ch * 4) * 4,
                   Qg + (size_t)(b * Sq + q0 + r) * Eq + h * 64 + ch * 4);
    }
    load_kv(0, 0);   // Q chunks fold into this same commit group

    float m0 = -INFINITY, m1 = -INFINITY;
    float l0 = 0.f, l1 = 0.f;
    float acc_o[4][4] = {};

    const int rloc = wm * 16 + qr;
    const int NT = Sq / KTL;

    for (int kt = 0; kt < NT; kt++) {
        const int buf = kt & 1;
        cp_wait<0>();          // only one group ever in flight -> exact
        __syncthreads();
        if (kt + 1 < NT) load_kv(kt + 1, buf ^ 1);   // overlaps entire tile compute

        float* Kb = Ks + (size_t)buf * KTL * QS;
        float* Vb = Vts + (size_t)buf * 64 * VS;

        // S = Q @ K^T
        float acc_s[8][4];
#pragma unroll
        for (int ni = 0; ni < 8; ni++)
#pragma unroll
            for (int k = 0; k < 4; k++) acc_s[ni][k] = 0.f;
#pragma unroll
        for (int ks = 0; ks < 8; ks++) {
            float a[4];
            int ab = rloc * QS + ks * 8 + qc;
            a[0] = Qs[ab]; a[1] = Qs[ab + 8 * QS]; a[2] = Qs[ab + 4]; a[3] = Qs[ab + 8 * QS + 4];
#pragma unroll
            for (int ni = 0; ni < 8; ni++) {
                int bb = (wn * 64 + ni * 8 + qr) * QS + ks * 8 + qc;
                float bf[2] = { Kb[bb], Kb[bb + 4] };
                mma_tf32(acc_s[ni], a, bf);
            }
        }

        // mask + rsqrt, row max
        float mr0 = -INFINITY, mr1 = -INFINITY;
#pragma unroll
        for (int ni = 0; ni < 8; ni++) {
            int colg = kt * KTL + wn * 64 + ni * 8 + qc * 2;
            int mk0 = mask[b * Sq + colg], mk1 = mask[b * Sq + colg + 1];
            float s0 = mk0 ? rsqrtf(acc_s[ni][0]) : -INFINITY;
            float s1 = mk1 ? rsqrtf(acc_s[ni][1]) : -INFINITY;
            float s2 = mk0 ? rsqrtf(acc_s[ni][2]) : -INFINITY;
            float s3 = mk1 ? rsqrtf(acc_s[ni][3]) : -INFINITY;
            acc_s[ni][0] = s0; acc_s[ni][1] = s1; acc_s[ni][2] = s2; acc_s[ni][3] = s3;
            mr0 = fmaxf(mr0, fmaxf(s0, s1));
            mr1 = fmaxf(mr1, fmaxf(s2, s3));
        }
#pragma unroll
        for (int o = 1; o < 4; o <<= 1) {
            mr0 = fmaxf(mr0, __shfl_xor_sync(0xffffffffu, mr0, o));
            mr1 = fmaxf(mr1, __shfl_xor_sync(0xffffffffu, mr1, o));
        }
        if (qc == 0) { tmpM[wn * 64 + rloc] = mr0; tmpM[wn * 64 + rloc + 8] = mr1; }
        __syncthreads();
        float mt0 = fmaxf(tmpM[rloc],     tmpM[64 + rloc]);
        float mt1 = fmaxf(tmpM[rloc + 8], tmpM[64 + rloc + 8]);
        float mn0 = fmaxf(m0, mt0), mn1 = fmaxf(m1, mt1);
        float mn0s = (mn0 == -INFINITY) ? 0.f : mn0;
        float mn1s = (mn1 == -INFINITY) ? 0.f : mn1;
        float sc0 = __expf(m0 - mn0s);
        float sc1 = __expf(m1 - mn1s);
        m0 = mn0; m1 = mn1;

        // exp, row sum, store P (tf32-rounded)
        float sr0 = 0.f, sr1 = 0.f;
#pragma unroll
        for (int ni = 0; ni < 8; ni++) {
            float p0 = __expf(acc_s[ni][0] - mn0s);
            float p1 = __expf(acc_s[ni][1] - mn0s);
            float p2 = __expf(acc_s[ni][2] - mn1s);
            float p3 = __expf(acc_s[ni][3] - mn1s);
            sr0 += p0 + p1; sr1 += p2 + p3;
            int colp = wn * 64 + ni * 8 + qc * 2;
            Ps[rloc * VS + colp]           = tf32r(p0);
            Ps[rloc * VS + colp + 1]       = tf32r(p1);
            Ps[(rloc + 8) * VS + colp]     = tf32r(p2);
            Ps[(rloc + 8) * VS + colp + 1] = tf32r(p3);
        }
#pragma unroll
        for (int o = 1; o < 4; o <<= 1) {
            sr0 += __shfl_xor_sync(0xffffffffu, sr0, o);
            sr1 += __shfl_xor_sync(0xffffffffu, sr1, o);
        }
        if (qc == 0) { tmpS[wn * 64 + rloc] = sr0; tmpS[wn * 64 + rloc + 8] = sr1; }
        __syncthreads();
        l0 = l0 * sc0 + tmpS[rloc]     + tmpS[64 + rloc];
        l1 = l1 * sc1 + tmpS[rloc + 8] + tmpS[64 + rloc + 8];

        // rescale O
#pragma unroll
        for (int ni = 0; ni < 4; ni++) {
            acc_o[ni][0] *= sc0; acc_o[ni][1] *= sc0;
            acc_o[ni][2] *= sc1; acc_o[ni][3] *= sc1;
        }

        // O += P @ V
#pragma unroll
        for (int ks = 0; ks < 16; ks++) {
            float a[4];
            int ab = rloc * VS + ks * 8 + qc;
            a[0] = Ps[ab]; a[1] = Ps[ab + 8 * VS]; a[2] = Ps[ab + 4]; a[3] = Ps[ab + 8 * VS + 4];
#pragma unroll
            for (int ni = 0; ni < 4; ni++) {
                int bb = (wn * 32 + ni * 8 + qr) * VS + ks * 8 + qc;
                float bf[2] = { Vb[bb], Vb[bb + 4] };
                mma_tf32(acc_o[ni], a, bf);
            }
        }
        __syncthreads();   // Ps reused next iter; Kb/Vb write target differs (double buffer)
    }

    // epilogue
    float inv0 = 1.f / l0, inv1 = 1.f / l1;
#pragma unroll
    for (int ni = 0; ni < 4; ni++) {
        int col = h * 64 + wn * 32 + ni * 8 + qc * 2;
        size_t r = (size_t)(b * Sq + q0 + rloc);
        *(float2*)(ctx + r * Eq + col) =
            make_float2(tf32r(acc_o[ni][0] * inv0), tf32r(acc_o[ni][1] * inv0));
        *(float2*)(ctx + (r + 8) * Eq + col) =
            make_float2(tf32r(acc_o[ni][2] * inv1), tf32r(acc_o[ni][3] * inv1));
    }
}

// ---------------- out = LayerNorm(A + R); optional tf32-rounded copy ----------------
__global__ void __launch_bounds__(256)
add_ln_kernel(const float* __restrict__ A, const float* __restrict__ R,
              const float* __restrict__ g, const float* __restrict__ be,
              float* __restrict__ out, float* __restrict__ out_r)
{
    const size_t row = blockIdx.x;
    const int tid = threadIdx.x;
    const int lane = tid & 31, warp = tid >> 5;
    __shared__ float red[8];
    const float* pa = A + row * Eq;
    const float* pr = R + row * Eq;

    float v[4];
    float s = 0.f;
#pragma unroll
    for (int i = 0; i < 4; i++) {
        v[i] = pa[tid + i * 256] + pr[tid + i * 256];
        s += v[i];
    }
#pragma unroll
    for (int o = 16; o; o >>= 1) s += __shfl_xor_sync(0xffffffffu, s, o);
    if (lane == 0) red[warp] = s;
    __syncthreads();
    if (tid == 0) {
        float t = 0.f;
#pragma unroll
        for (int i = 0; i < 8; i++) t += red[i];
        red[0] = t;
    }
    __syncthreads();
    const float mean = red[0] * (1.f / Eq);
    __syncthreads();

    float s2 = 0.f;
#pragma unroll
    for (int i = 0; i < 4; i++) {
        float d = v[i] - mean;
        s2 += d * d;
    }
#pragma unroll
    for (int o = 16; o; o >>= 1) s2 += __shfl_xor_sync(0xffffffffu, s2, o);
    if (lane == 0) red[warp] = s2;
    __syncthreads();
    if (tid == 0) {
        float t = 0.f;
#pragma unroll
        for (int i = 0; i < 8; i++) t += red[i];
        red[0] = t;
    }
    __syncthreads();
    const float inv = rsqrtf(red[0] * (1.f / Eq) + LN_EPS);

#pragma unroll
    for (int i = 0; i < 4; i++) {
        int c = tid + i * 256;
        float o = (v[i] - mean) * inv * g[c] + be[c];
        out[row * Eq + c] = o;
        if (out_r) out_r[row * Eq + c] = tf32r(o);
    }
}

// ---------------- host launch ----------------
extern "C" void kernel_launch(void* const* d_in, const int* in_sizes, int n_in,
                              void* d_out, int out_size)
{
    const float* value = (const float*)d_in[0];
    const float* key   = (const float*)d_in[1];
    const float* query = (const float*)d_in[2];
    const int*   mask  = (const int*)d_in[3];
    const float* Wv = (const float*)d_in[4];
    const float* bv = (const float*)d_in[5];
    const float* Wk = (const float*)d_in[6];
    const float* bk = (const float*)d_in[7];
    const float* Wq = (const float*)d_in[8];
    const float* bq = (const float*)d_in[9];
    const float* Wo = (const float*)d_in[10];
    const float* bo = (const float*)d_in[11];
    const float* W1 = (const float*)d_in[12];
    const float* b1 = (const float*)d_in[13];
    const float* W2 = (const float*)d_in[14];
    const float* b2 = (const float*)d_in[15];
    const float* g1  = (const float*)d_in[16];
    const float* be1 = (const float*)d_in[17];
    const float* g2  = (const float*)d_in[18];
    const float* be2 = (const float*)d_in[19];
    float* out = (float*)d_out;

    float *pV, *pK, *pQ, *pVt, *pCtx, *pAo, *pX, *pXr, *pH, *pFf;
    float *pVr, *pKr, *pQr;
    float *pWvt, *pWkt, *pWqt, *pWot, *pW1t, *pW2t;
    cudaGetSymbolAddress((void**)&pV,   g_V);
    cudaGetSymbolAddress((void**)&pK,   g_K);
    cudaGetSymbolAddress((void**)&pQ,   g_Q);
    cudaGetSymbolAddress((void**)&pVt,  g_Vt);
    cudaGetSymbolAddress((void**)&pCtx, g_ctx);
    cudaGetSymbolAddress((void**)&pAo,  g_ao);
    cudaGetSymbolAddress((void**)&pX,   g_x);
    cudaGetSymbolAddress((void**)&pXr,  g_xr);
    cudaGetSymbolAddress((void**)&pH,   g_h);
    cudaGetSymbolAddress((void**)&pFf,  g_ff);
    cudaGetSymbolAddress((void**)&pVr,  g_vr);
    cudaGetSymbolAddress((void**)&pKr,  g_kr);
    cudaGetSymbolAddress((void**)&pQr,  g_qr);
    cudaGetSymbolAddress((void**)&pWvt, g_Wvt);
    cudaGetSymbolAddress((void**)&pWkt, g_Wkt);
    cudaGetSymbolAddress((void**)&pWqt, g_Wqt);
    cudaGetSymbolAddress((void**)&pWot, g_Wot);
    cudaGetSymbolAddress((void**)&pW1t, g_W1t);
    cudaGetSymbolAddress((void**)&pW2t, g_W2t);

    cudaFuncSetAttribute(gemm_tf32, cudaFuncAttributeMaxDynamicSharedMemorySize, GSMEM);
    cudaFuncSetAttribute(flash_kernel, cudaFuncAttributeMaxDynamicSharedMemorySize, FSMEM);

    const int M = Bq * Sq;  // 4096
    dim3 blk(256);

    // weight transpose + tf32 rounding
    transpose_tf32_kernel<<<dim3(Eq / 32, Eq / 32), blk>>>(Wv, pWvt, Eq, Eq);
    transpose_tf32_kernel<<<dim3(Eq / 32, Eq / 32), blk>>>(Wk, pWkt, Eq, Eq);
    transpose_tf32_kernel<<<dim3(Eq / 32, Eq / 32), blk>>>(Wq, pWqt, Eq, Eq);
    transpose_tf32_kernel<<<dim3(Eq / 32, Eq / 32), blk>>>(Wo, pWot, Eq, Eq);
    transpose_tf32_kernel<<<dim3(FFq / 32, Eq / 32), blk>>>(W1, pW1t, Eq, FFq);
    transpose_tf32_kernel<<<dim3(Eq / 32, FFq / 32), blk>>>(W2, pW2t, FFq, Eq);

    // round activations feeding QKV GEMMs
    {
        int n4 = M * Eq / 4;
        round_tf32_kernel<<<(n4 + 255) / 256, 256>>>(value, pVr, n4);
        round_tf32_kernel<<<(n4 + 255) / 256, 256>>>(key,   pKr, n4);
        round_tf32_kernel<<<(n4 + 255) / 256, 256>>>(query, pQr, n4);
    }

    // QKV projections (tf32 MMA), outputs tf32-rounded for attention
    dim3 grid_e(Eq / 128, M / 128);
    gemm_tf32<<<grid_e, blk, GSMEM>>>(pVr, pWvt, bv, pV, M, Eq, Eq, 0, 1);
    gemm_tf32<<<grid_e, blk, GSMEM>>>(pKr, pWkt, bk, pK, M, Eq, Eq, 0, 1);
    gemm_tf32<<<grid_e, blk, GSMEM>>>(pQr, pWqt, bq, pQ, M, Eq, Eq, 0, 1);

    // V transpose per batch
    vtrans_kernel<<<dim3(Sq / 32, Eq / 32, Bq), blk>>>(pV, pVt);

    // fused flash attention -> ctx (tf32-rounded)
    flash_kernel<<<dim3(Sq / QT, Bq * Hh), blk, FSMEM>>>(pQ, pK, pVt, mask, pCtx);

    // output projection
    gemm_tf32<<<grid_e, blk, GSMEM>>>(pCtx, pWot, bo, pAo, M, Eq, Eq, 0, 0);

    // x = LN(attn_out + query); tf32-rounded copy for FFN1
    add_ln_kernel<<<M, blk>>>(pAo, query, g1, be1, pX, pXr);

    // FFN1
    dim3 grid_ff1(FFq / 128, M / 128);
    gemm_tf32<<<grid_ff1, blk, GSMEM>>>(pXr, pW1t, b1, pH, M, Eq, FFq, 1, 1);

    // FFN2
    dim3 grid_ff2(Eq / 128, M / 128);
    gemm_tf32<<<grid_ff2, blk, GSMEM>>>(pH, pW2t, b2, pFf, M, FFq, Eq, 0, 0);

    // out = LN(ff + x)
    add_ln_kernel<<<M, blk>>>(pFf, pX, g2, be2, out, nullptr);
}

// round 8
// speedup vs baseline: 1.3495x; 1.0755x over previous
#include <cuda_runtime.h>
#include <math.h>
#include <stdint.h>

// ---------------- problem dims ----------------
#define Bq 4
#define Sq 1024
#define Eq 1024
#define Hh 16
#define Dd 64
#define FFq 4096
#define LN_EPS 1e-5f

// ---------------- scratch (device globals) ----------------
__device__ float g_V[Bq * Sq * Eq];
__device__ float g_K[Bq * Sq * Eq];
__device__ float g_Q[Bq * Sq * Eq];
__device__ float g_Vt[Bq * Sq * Eq];
__device__ float g_ctx[Bq * Sq * Eq];
__device__ float g_ao[Bq * Sq * Eq];
__device__ float g_x[Bq * Sq * Eq];
__device__ float g_xr[Bq * Sq * Eq];
__device__ float g_h[(size_t)Bq * Sq * FFq];
__device__ float g_ff[Bq * Sq * Eq];
__device__ float g_vr[Bq * Sq * Eq];
__device__ float g_kr[Bq * Sq * Eq];
__device__ float g_qr[Bq * Sq * Eq];
__device__ float g_Wvt[Eq * Eq];
__device__ float g_Wkt[Eq * Eq];
__device__ float g_Wqt[Eq * Eq];
__device__ float g_Wot[Eq * Eq];
__device__ float g_W1t[(size_t)Eq * FFq];
__device__ float g_W2t[(size_t)Eq * FFq];

// ---------------- PTX helpers ----------------
__device__ __forceinline__ uint32_t smem_u32(const void* p) {
    uint32_t a;
    asm("{ .reg .u64 t; cvta.to.shared.u64 t, %1; cvt.u32.u64 %0, t; }" : "=r"(a) : "l"(p));
    return a;
}
__device__ __forceinline__ void cp_async16(uint32_t dst, const void* src) {
    asm volatile("cp.async.ca.shared.global [%0], [%1], 16;" :: "r"(dst), "l"(src));
}
__device__ __forceinline__ void cp_commit() { asm volatile("cp.async.commit_group;"); }
template <int N>
__device__ __forceinline__ void cp_wait() { asm volatile("cp.async.wait_group %0;" :: "n"(N)); }

__device__ __forceinline__ float tf32r(float x) {
    uint32_t u;
    asm("cvt.rna.tf32.f32 %0, %1;" : "=r"(u) : "f"(x));
    return __uint_as_float(u);
}
__device__ __forceinline__ void ldsm_x4u(uint32_t* r, uint32_t addr) {
    asm volatile("ldmatrix.sync.aligned.m8n8.x4.shared.b16 {%0,%1,%2,%3}, [%4];"
        : "=r"(r[0]), "=r"(r[1]), "=r"(r[2]), "=r"(r[3]) : "r"(addr));
}
__device__ __forceinline__ void mma_tf32u(float* c, const uint32_t* a, uint32_t b0, uint32_t b1) {
    asm volatile(
        "mma.sync.aligned.m16n8k8.row.col.f32.tf32.tf32.f32 "
        "{%0,%1,%2,%3}, {%4,%5,%6,%7}, {%8,%9}, {%0,%1,%2,%3};"
        : "+f"(c[0]), "+f"(c[1]), "+f"(c[2]), "+f"(c[3])
        : "r"(a[0]), "r"(a[1]), "r"(a[2]), "r"(a[3]), "r"(b0), "r"(b1));
}
__device__ __forceinline__ void mma_tf32(float* c, const float* a, const float* b) {
    asm volatile(
        "mma.sync.aligned.m16n8k8.row.col.f32.tf32.tf32.f32 "
        "{%0,%1,%2,%3}, {%4,%5,%6,%7}, {%8,%9}, {%0,%1,%2,%3};"
        : "+f"(c[0]), "+f"(c[1]), "+f"(c[2]), "+f"(c[3])
        : "r"(__float_as_uint(a[0])), "r"(__float_as_uint(a[1])),
          "r"(__float_as_uint(a[2])), "r"(__float_as_uint(a[3])),
          "r"(__float_as_uint(b[0])), "r"(__float_as_uint(b[1])));
}

// ---------------- tf32 rounding pass ----------------
__global__ void __launch_bounds__(256)
round_tf32_kernel(const float* __restrict__ in, float* __restrict__ out, int n4)
{
    int i = blockIdx.x * 256 + threadIdx.x;
    if (i >= n4) return;
    float4 v = ((const float4*)in)[i];
    v.x = tf32r(v.x); v.y = tf32r(v.y); v.z = tf32r(v.z); v.w = tf32r(v.w);
    ((float4*)out)[i] = v;
}

// ---------------- W[K,N] fp32 -> Wt[N,K] tf32-rounded ----------------
__global__ void __launch_bounds__(256)
transpose_tf32_kernel(const float* __restrict__ W, float* __restrict__ Wt, int K, int N)
{
    __shared__ float t[32][33];
    const int k0 = blockIdx.y * 32, n0 = blockIdx.x * 32;
    const int tx = threadIdx.x & 31, ty = threadIdx.x >> 5;
#pragma unroll
    for (int i = 0; i < 32; i += 8)
        t[ty + i][tx] = W[(size_t)(k0 + ty + i) * N + n0 + tx];
    __syncthreads();
#pragma unroll
    for (int i = 0; i < 32; i += 8)
        Wt[(size_t)(n0 + ty + i) * K + k0 + tx] = tf32r(t[tx][ty + i]);
}

// ---------------- per-batch transpose: Vt[(b*E+c)][k] = V[(b*S+k)][c] ----------------
__global__ void __launch_bounds__(256)
vtrans_kernel(const float* __restrict__ V, float* __restrict__ Vt)
{
    __shared__ float t[32][33];
    const int b = blockIdx.z;
    const int k0 = blockIdx.x * 32, c0 = blockIdx.y * 32;
    const int tx = threadIdx.x & 31, ty = threadIdx.x >> 5;
#pragma unroll
    for (int i = 0; i < 32; i += 8)
        t[ty + i][tx] = V[(size_t)(b * Sq + k0 + ty + i) * Eq + c0 + tx];
    __syncthreads();
#pragma unroll
    for (int i = 0; i < 32; i += 8)
        Vt[(size_t)(b * Eq + c0 + ty + i) * Sq + k0 + tx] = t[tx][ty + i];
}

// ---------------- tf32 MMA GEMM, ldmatrix fragment feed ----------------
// CTA 128x128, kt=32, 2-stage cp.async (R5 structure), 8 warps 4Mx2N.
// Fragments via ldmatrix.m8n8 (.b16 on fp32 bits): A 2x ldsm.x4, B 4x ldsm.x4 per k8.
#define KT 32
#define PAD 36
#define GSMEM (2 * 2 * 128 * PAD * 4)   // 73728 B

__global__ void __launch_bounds__(256)
gemm_tf32(const float* __restrict__ A, const float* __restrict__ Bt,
          const float* __restrict__ bias, float* __restrict__ C,
          int M, int K, int N, int relu, int round_out)
{
    extern __shared__ float sm[];
    const int tid = threadIdx.x;
    const int wid = tid >> 5, lane = tid & 31;
    const int wm = wid & 3, wn = wid >> 2;
    const int row0 = blockIdx.y * 128;
    const int col0 = blockIdx.x * 128;

    const uint32_t sbase = smem_u32(sm);
    const uint32_t MATB = 128 * PAD * 4;

    float acc[2][8][4];
#pragma unroll
    for (int i = 0; i < 2; i++)
#pragma unroll
        for (int j = 0; j < 8; j++)
#pragma unroll
            for (int k = 0; k < 4; k++) acc[i][j][k] = 0.f;

    const int NC = K / KT;

    auto load_tile = [&](int c, int buf) {
        const float* Ag = A  + (size_t)row0 * K + c * KT;
        const float* Bg = Bt + (size_t)col0 * K + c * KT;
        const uint32_t ab = sbase + (uint32_t)buf * 2 * MATB;
        const uint32_t bb = ab + MATB;
#pragma unroll
        for (int i = 0; i < 4; i++) {
            int id = tid + i * 256;
            int r = id >> 3, c4 = id & 7;
            uint32_t off = (uint32_t)(r * PAD + c4 * 4) * 4;
            cp_async16(ab + off, Ag + (size_t)r * K + c4 * 4);
            cp_async16(bb + off, Bg + (size_t)r * K + c4 * 4);
        }
        cp_commit();
    };

    load_tile(0, 0);

    // ldmatrix per-lane source rows/cols (fp32 units)
    const int arow = wm * 32 + (lane & 15);          // + mi*16
    const int acol = (lane >> 4) << 2;               // 0 or 4
    const int brow = wn * 64 + ((lane >> 4) << 3) + (lane & 7);  // + nip*16
    const int bcol = ((lane >> 3) & 1) << 2;         // 0 or 4

    for (int c = 0; c < NC; c++) {
        const int buf = c & 1;
        if (c + 1 < NC) { load_tile(c + 1, buf ^ 1); cp_wait<1>(); }
        else            { cp_wait<0>(); }
        __syncthreads();

        const uint32_t au = sbase + (uint32_t)buf * 2 * MATB;
        const uint32_t bu = au + MATB;

#pragma unroll
        for (int ks = 0; ks < 4; ks++) {
            const int ck = ks * 8;
            uint32_t afr[2][4], bfr[4][4];
#pragma unroll
            for (int mi = 0; mi < 2; mi++)
                ldsm_x4u(afr[mi], au + (uint32_t)(((arow + mi * 16) * PAD) + ck + acol) * 4);
#pragma unroll
            for (int nip = 0; nip < 4; nip++)
                ldsm_x4u(bfr[nip], bu + (uint32_t)(((brow + nip * 16) * PAD) + ck + bcol) * 4);
#pragma unroll
            for (int mi = 0; mi < 2; mi++)
#pragma unroll
                for (int ni = 0; ni < 8; ni++)
                    mma_tf32u(acc[mi][ni], afr[mi],
                              bfr[ni >> 1][(ni & 1) * 2], bfr[ni >> 1][(ni & 1) * 2 + 1]);
        }
        __syncthreads();
    }

    const int qr = lane >> 2;
    const int qc = (lane & 3) * 2;
#pragma unroll
    for (int mi = 0; mi < 2; mi++) {
#pragma unroll
        for (int ni = 0; ni < 8; ni++) {
            int col = col0 + wn * 64 + ni * 8 + qc;
            float b0 = bias[col], b1 = bias[col + 1];
            int r0 = row0 + wm * 32 + mi * 16 + qr;
            float v0 = acc[mi][ni][0] + b0;
            float v1 = acc[mi][ni][1] + b1;
            float v2 = acc[mi][ni][2] + b0;
            float v3 = acc[mi][ni][3] + b1;
            if (relu) {
                v0 = fmaxf(v0, 0.f); v1 = fmaxf(v1, 0.f);
                v2 = fmaxf(v2, 0.f); v3 = fmaxf(v3, 0.f);
            }
            if (round_out) {
                v0 = tf32r(v0); v1 = tf32r(v1);
                v2 = tf32r(v2); v3 = tf32r(v3);
            }
            *(float2*)(C + (size_t)r0 * N + col)       = make_float2(v0, v1);
            *(float2*)(C + (size_t)(r0 + 8) * N + col) = make_float2(v2, v3);
        }
    }
}

// ---------------- fused flash attention (R5 version, known-good) ----------------
#define QT 64
#define KTL 128
#define QS 68
#define VS 132
#define FSMEM ((QT*QS + KTL*QS + 64*VS + QT*VS + 256) * 4)

__global__ void __launch_bounds__(256)
flash_kernel(const float* __restrict__ Qg, const float* __restrict__ Kg,
             const float* __restrict__ Vtg, const int* __restrict__ mask,
             float* __restrict__ ctx)
{
    extern __shared__ float sf[];
    float* Qs  = sf;                   // 64 x QS
    float* Ks  = Qs + QT * QS;         // 128 x QS
    float* Vts = Ks + KTL * QS;        // 64 x VS
    float* Ps  = Vts + 64 * VS;        // 64 x VS
    float* tmpM = Ps + QT * VS;        // 128
    float* tmpS = tmpM + 128;          // 128

    const int tid = threadIdx.x;
    const int wid = tid >> 5, lane = tid & 31;
    const int wm = wid & 3, wn = wid >> 2;
    const int qr = lane >> 2, qc = lane & 3;
    const int bh = blockIdx.y, b = bh >> 4, h = bh & 15;
    const int q0 = blockIdx.x * QT;

    const uint32_t qs_u = smem_u32(Qs), ks_u = smem_u32(Ks), vs_u = smem_u32(Vts);

    // load Q tile (once)
#pragma unroll
    for (int i = 0; i < 4; i++) {
        int id = tid + i * 256;
        int r = id >> 4, ch = id & 15;
        cp_async16(qs_u + (uint32_t)(r * QS + ch * 4) * 4,
                   Qg + (size_t)(b * Sq + q0 + r) * Eq + h * 64 + ch * 4);
    }
    cp_commit();

    float m0 = -INFINITY, m1 = -INFINITY;
    float l0 = 0.f, l1 = 0.f;
    float acc_o[4][4] = {};

    const int rloc = wm * 16 + qr;

    for (int kt = 0; kt < Sq / KTL; kt++) {
        // load K tile and Vt tile
#pragma unroll
        for (int i = 0; i < 8; i++) {
            int id = tid + i * 256;
            int r = id >> 4, ch = id & 15;
            cp_async16(ks_u + (uint32_t)(r * QS + ch * 4) * 4,
                       Kg + (size_t)(b * Sq + kt * KTL + r) * Eq + h * 64 + ch * 4);
        }
#pragma unroll
        for (int i = 0; i < 8; i++) {
            int id = tid + i * 256;
            int r = id >> 5, ch = id & 31;
            cp_async16(vs_u + (uint32_t)(r * VS + ch * 4) * 4,
                       Vtg + (size_t)(b * Eq + h * 64 + r) * Sq + kt * KTL + ch * 4);
        }
        cp_commit();
        cp_wait<0>();
        __syncthreads();

        // S = Q @ K^T
        float acc_s[8][4];
#pragma unroll
        for (int ni = 0; ni < 8; ni++)
#pragma unroll
            for (int k = 0; k < 4; k++) acc_s[ni][k] = 0.f;
#pragma unroll
        for (int ks = 0; ks < 8; ks++) {
            float a[4];
            int ab = rloc * QS + ks * 8 + qc;
            a[0] = Qs[ab]; a[1] = Qs[ab + 8 * QS]; a[2] = Qs[ab + 4]; a[3] = Qs[ab + 8 * QS + 4];
#pragma unroll
            for (int ni = 0; ni < 8; ni++) {
                int bb = (wn * 64 + ni * 8 + qr) * QS + ks * 8 + qc;
                float bf[2] = { Ks[bb], Ks[bb + 4] };
                mma_tf32(acc_s[ni], a, bf);
            }
        }

        // mask + rsqrt, row max
        float mr0 = -INFINITY, mr1 = -INFINITY;
#pragma unroll
        for (int ni = 0; ni < 8; ni++) {
            int colg = kt * KTL + wn * 64 + ni * 8 + qc * 2;
            int mk0 = mask[b * Sq + colg], mk1 = mask[b * Sq + colg + 1];
            float s0 = mk0 ? rsqrtf(acc_s[ni][0]) : -INFINITY;
            float s1 = mk1 ? rsqrtf(acc_s[ni][1]) : -INFINITY;
            float s2 = mk0 ? rsqrtf(acc_s[ni][2]) : -INFINITY;
            float s3 = mk1 ? rsqrtf(acc_s[ni][3]) : -INFINITY;
            acc_s[ni][0] = s0; acc_s[ni][1] = s1; acc_s[ni][2] = s2; acc_s[ni][3] = s3;
            mr0 = fmaxf(mr0, fmaxf(s0, s1));
            mr1 = fmaxf(mr1, fmaxf(s2, s3));
        }
#pragma unroll
        for (int o = 1; o < 4; o <<= 1) {
            mr0 = fmaxf(mr0, __shfl_xor_sync(0xffffffffu, mr0, o));
            mr1 = fmaxf(mr1, __shfl_xor_sync(0xffffffffu, mr1, o));
        }
        if (qc == 0) { tmpM[wn * 64 + rloc] = mr0; tmpM[wn * 64 + rloc + 8] = mr1; }
        __syncthreads();
        float mt0 = fmaxf(tmpM[rloc],     tmpM[64 + rloc]);
        float mt1 = fmaxf(tmpM[rloc + 8], tmpM[64 + rloc + 8]);
        float mn0 = fmaxf(m0, mt0), mn1 = fmaxf(m1, mt1);
        float mn0s = (mn0 == -INFINITY) ? 0.f : mn0;
        float mn1s = (mn1 == -INFINITY) ? 0.f : mn1;
        float sc0 = __expf(m0 - mn0s);
        float sc1 = __expf(m1 - mn1s);
        m0 = mn0; m1 = mn1;

        // exp, row sum, store P (tf32-rounded)
        float sr0 = 0.f, sr1 = 0.f;
#pragma unroll
        for (int ni = 0; ni < 8; ni++) {
            float p0 = __expf(acc_s[ni][0] - mn0s);
            float p1 = __expf(acc_s[ni][1] - mn0s);
            float p2 = __expf(acc_s[ni][2] - mn1s);
            float p3 = __expf(acc_s[ni][3] - mn1s);
            sr0 += p0 + p1; sr1 += p2 + p3;
            int colp = wn * 64 + ni * 8 + qc * 2;
            Ps[rloc * VS + colp]           = tf32r(p0);
            Ps[rloc * VS + colp + 1]       = tf32r(p1);
            Ps[(rloc + 8) * VS + colp]     = tf32r(p2);
            Ps[(rloc + 8) * VS + colp + 1] = tf32r(p3);
        }
#pragma unroll
        for (int o = 1; o < 4; o <<= 1) {
            sr0 += __shfl_xor_sync(0xffffffffu, sr0, o);
            sr1 += __shfl_xor_sync(0xffffffffu, sr1, o);
        }
        if (qc == 0) { tmpS[wn * 64 + rloc] = sr0; tmpS[wn * 64 + rloc + 8] = sr1; }
        __syncthreads();
        l0 = l0 * sc0 + tmpS[rloc]     + tmpS[64 + rloc];
        l1 = l1 * sc1 + tmpS[rloc + 8] + tmpS[64 + rloc + 8];

        // rescale O
#pragma unroll
        for (int ni = 0; ni < 4; ni++) {
            acc_o[ni][0] *= sc0; acc_o[ni][1] *= sc0;
            acc_o[ni][2] *= sc1; acc_o[ni][3] *= sc1;
        }

        // O += P @ V
#pragma unroll
        for (int ks = 0; ks < 16; ks++) {
            float a[4];
            int ab = rloc * VS + ks * 8 + qc;
            a[0] = Ps[ab]; a[1] = Ps[ab + 8 * VS]; a[2] = Ps[ab + 4]; a[3] = Ps[ab + 8 * VS + 4];
#pragma unroll
            for (int ni = 0; ni < 4; ni++) {
                int bb = (wn * 32 + ni * 8 + qr) * VS + ks * 8 + qc;
                float bf[2] = { Vts[bb], Vts[bb + 4] };
                mma_tf32(acc_o[ni], a, bf);
            }
        }
        __syncthreads();
    }

    // epilogue
    float inv0 = 1.f / l0, inv1 = 1.f / l1;
#pragma unroll
    for (int ni = 0; ni < 4; ni++) {
        int col = h * 64 + wn * 32 + ni * 8 + qc * 2;
        size_t r = (size_t)(b * Sq + q0 + rloc);
        *(float2*)(ctx + r * Eq + col) =
            make_float2(tf32r(acc_o[ni][0] * inv0), tf32r(acc_o[ni][1] * inv0));
        *(float2*)(ctx + (r + 8) * Eq + col) =
            make_float2(tf32r(acc_o[ni][2] * inv1), tf32r(acc_o[ni][3] * inv1));
    }
}

// ---------------- out = LayerNorm(A + R); optional tf32-rounded copy ----------------
__global__ void __launch_bounds__(256)
add_ln_kernel(const float* __restrict__ A, const float* __restrict__ R,
              const float* __restrict__ g, const float* __restrict__ be,
              float* __restrict__ out, float* __restrict__ out_r)
{
    const size_t row = blockIdx.x;
    const int tid = threadIdx.x;
    const int lane = tid & 31, warp = tid >> 5;
    __shared__ float red[8];
    const float* pa = A + row * Eq;
    const float* pr = R + row * Eq;

    float v[4];
    float s = 0.f;
#pragma unroll
    for (int i = 0; i < 4; i++) {
        v[i] = pa[tid + i * 256] + pr[tid + i * 256];
        s += v[i];
    }
#pragma unroll
    for (int o = 16; o; o >>= 1) s += __shfl_xor_sync(0xffffffffu, s, o);
    if (lane == 0) red[warp] = s;
    __syncthreads();
    if (tid == 0) {
        float t = 0.f;
#pragma unroll
        for (int i = 0; i < 8; i++) t += red[i];
        red[0] = t;
    }
    __syncthreads();
    const float mean = red[0] * (1.f / Eq);
    __syncthreads();

    float s2 = 0.f;
#pragma unroll
    for (int i = 0; i < 4; i++) {
        float d = v[i] - mean;
        s2 += d * d;
    }
#pragma unroll
    for (int o = 16; o; o >>= 1) s2 += __shfl_xor_sync(0xffffffffu, s2, o);
    if (lane == 0) red[warp] = s2;
    __syncthreads();
    if (tid == 0) {
        float t = 0.f;
#pragma unroll
        for (int i = 0; i < 8; i++) t += red[i];
        red[0] = t;
    }
    __syncthreads();
    const float inv = rsqrtf(red[0] * (1.f / Eq) + LN_EPS);

#pragma unroll
    for (int i = 0; i < 4; i++) {
        int c = tid + i * 256;
        float o = (v[i] - mean) * inv * g[c] + be[c];
        out[row * Eq + c] = o;
        if (out_r) out_r[row * Eq + c] = tf32r(o);
    }
}

// ---------------- host launch ----------------
extern "C" void kernel_launch(void* const* d_in, const int* in_sizes, int n_in,
                              void* d_out, int out_size)
{
    const float* value = (const float*)d_in[0];
    const float* key   = (const float*)d_in[1];
    const float* query = (const float*)d_in[2];
    const int*   mask  = (const int*)d_in[3];
    const float* Wv = (const float*)d_in[4];
    const float* bv = (const float*)d_in[5];
    const float* Wk = (const float*)d_in[6];
    const float* bk = (const float*)d_in[7];
    const float* Wq = (const float*)d_in[8];
    const float* bq = (const float*)d_in[9];
    const float* Wo = (const float*)d_in[10];
    const float* bo = (const float*)d_in[11];
    const float* W1 = (const float*)d_in[12];
    const float* b1 = (const float*)d_in[13];
    const float* W2 = (const float*)d_in[14];
    const float* b2 = (const float*)d_in[15];
    const float* g1  = (const float*)d_in[16];
    const float* be1 = (const float*)d_in[17];
    const float* g2  = (const float*)d_in[18];
    const float* be2 = (const float*)d_in[19];
    float* out = (float*)d_out;

    float *pV, *pK, *pQ, *pVt, *pCtx, *pAo, *pX, *pXr, *pH, *pFf;
    float *pVr, *pKr, *pQr;
    float *pWvt, *pWkt, *pWqt, *pWot, *pW1t, *pW2t;
    cudaGetSymbolAddress((void**)&pV,   g_V);
    cudaGetSymbolAddress((void**)&pK,   g_K);
    cudaGetSymbolAddress((void**)&pQ,   g_Q);
    cudaGetSymbolAddress((void**)&pVt,  g_Vt);
    cudaGetSymbolAddress((void**)&pCtx, g_ctx);
    cudaGetSymbolAddress((void**)&pAo,  g_ao);
    cudaGetSymbolAddress((void**)&pX,   g_x);
    cudaGetSymbolAddress((void**)&pXr,  g_xr);
    cudaGetSymbolAddress((void**)&pH,   g_h);
    cudaGetSymbolAddress((void**)&pFf,  g_ff);
    cudaGetSymbolAddress((void**)&pVr,  g_vr);
    cudaGetSymbolAddress((void**)&pKr,  g_kr);
    cudaGetSymbolAddress((void**)&pQr,  g_qr);
    cudaGetSymbolAddress((void**)&pWvt, g_Wvt);
    cudaGetSymbolAddress((void**)&pWkt, g_Wkt);
    cudaGetSymbolAddress((void**)&pWqt, g_Wqt);
    cudaGetSymbolAddress((void**)&pWot, g_Wot);
    cudaGetSymbolAddress((void**)&pW1t, g_W1t);
    cudaGetSymbolAddress((void**)&pW2t, g_W2t);

    cudaFuncSetAttribute(gemm_tf32, cudaFuncAttributeMaxDynamicSharedMemorySize, GSMEM);
    cudaFuncSetAttribute(flash_kernel, cudaFuncAttributeMaxDynamicSharedMemorySize, FSMEM);

    const int M = Bq * Sq;  // 4096
    dim3 blk(256);

    // weight transpose + tf32 rounding
    transpose_tf32_kernel<<<dim3(Eq / 32, Eq / 32), blk>>>(Wv, pWvt, Eq, Eq);
    transpose_tf32_kernel<<<dim3(Eq / 32, Eq / 32), blk>>>(Wk, pWkt, Eq, Eq);
    transpose_tf32_kernel<<<dim3(Eq / 32, Eq / 32), blk>>>(Wq, pWqt, Eq, Eq);
    transpose_tf32_kernel<<<dim3(Eq / 32, Eq / 32), blk>>>(Wo, pWot, Eq, Eq);
    transpose_tf32_kernel<<<dim3(FFq / 32, Eq / 32), blk>>>(W1, pW1t, Eq, FFq);
    transpose_tf32_kernel<<<dim3(Eq / 32, FFq / 32), blk>>>(W2, pW2t, FFq, Eq);

    // round activations feeding QKV GEMMs
    {
        int n4 = M * Eq / 4;
        round_tf32_kernel<<<(n4 + 255) / 256, 256>>>(value, pVr, n4);
        round_tf32_kernel<<<(n4 + 255) / 256, 256>>>(key,   pKr, n4);
        round_tf32_kernel<<<(n4 + 255) / 256, 256>>>(query, pQr, n4);
    }

    // QKV projections (tf32 MMA), outputs tf32-rounded for attention
    dim3 grid_e(Eq / 128, M / 128);
    gemm_tf32<<<grid_e, blk, GSMEM>>>(pVr, pWvt, bv, pV, M, Eq, Eq, 0, 1);
    gemm_tf32<<<grid_e, blk, GSMEM>>>(pKr, pWkt, bk, pK, M, Eq, Eq, 0, 1);
    gemm_tf32<<<grid_e, blk, GSMEM>>>(pQr, pWqt, bq, pQ, M, Eq, Eq, 0, 1);

    // V transpose per batch
    vtrans_kernel<<<dim3(Sq / 32, Eq / 32, Bq), blk>>>(pV, pVt);

    // fused flash attention -> ctx (tf32-rounded)
    flash_kernel<<<dim3(Sq / QT, Bq * Hh), blk, FSMEM>>>(pQ, pK, pVt, mask, pCtx);

    // output projection
    gemm_tf32<<<grid_e, blk, GSMEM>>>(pCtx, pWot, bo, pAo, M, Eq, Eq, 0, 0);

    // x = LN(attn_out + query); tf32-rounded copy for FFN1
    add_ln_kernel<<<M, blk>>>(pAo, query, g1, be1, pX, pXr);

    // FFN1
    dim3 grid_ff1(FFq / 128, M / 128);
    gemm_tf32<<<grid_ff1, blk, GSMEM>>>(pXr, pW1t, b1, pH, M, Eq, FFq, 1, 1);

    // FFN2
    dim3 grid_ff2(Eq / 128, M / 128);
    gemm_tf32<<<grid_ff2, blk, GSMEM>>>(pH, pW2t, b2, pFf, M, FFq, Eq, 0, 0);

    // out = LN(ff + x)
    add_ln_kernel<<<M, blk>>>(pFf, pX, g2, be2, out, nullptr);
}

// round 10
// speedup vs baseline: 1.3521x; 1.0019x over previous
#include <cuda_runtime.h>
#include <math.h>
#include <stdint.h>

// ---------------- problem dims ----------------
#define Bq 4
#define Sq 1024
#define Eq 1024
#define Hh 16
#define Dd 64
#define FFq 4096
#define LN_EPS 1e-5f

// ---------------- scratch (device globals) ----------------
__device__ float g_V[Bq * Sq * Eq];
__device__ float g_K[Bq * Sq * Eq];
__device__ float g_Q[Bq * Sq * Eq];
__device__ float g_Vt[Bq * Sq * Eq];
__device__ float g_ctx[Bq * Sq * Eq];
__device__ float g_ao[Bq * Sq * Eq];
__device__ float g_x[Bq * Sq * Eq];
__device__ float g_xr[Bq * Sq * Eq];
__device__ float g_h[(size_t)Bq * Sq * FFq];
__device__ float g_ff[Bq * Sq * Eq];
__device__ float g_vr[Bq * Sq * Eq];
__device__ float g_kr[Bq * Sq * Eq];
__device__ float g_qr[Bq * Sq * Eq];
__device__ float g_Wvt[Eq * Eq];
__device__ float g_Wkt[Eq * Eq];
__device__ float g_Wqt[Eq * Eq];
__device__ float g_Wot[Eq * Eq];
__device__ float g_W1t[(size_t)Eq * FFq];
__device__ float g_W2t[(size_t)Eq * FFq];

// ---------------- PTX helpers ----------------
__device__ __forceinline__ uint32_t smem_u32(const void* p) {
    uint32_t a;
    asm("{ .reg .u64 t; cvta.to.shared.u64 t, %1; cvt.u32.u64 %0, t; }" : "=r"(a) : "l"(p));
    return a;
}
__device__ __forceinline__ void cp_async16(uint32_t dst, const void* src) {
    asm volatile("cp.async.ca.shared.global [%0], [%1], 16;" :: "r"(dst), "l"(src));
}
__device__ __forceinline__ void cp_commit() { asm volatile("cp.async.commit_group;"); }
template <int N>
__device__ __forceinline__ void cp_wait() { asm volatile("cp.async.wait_group %0;" :: "n"(N)); }

__device__ __forceinline__ float tf32r(float x) {
    uint32_t u;
    asm("cvt.rna.tf32.f32 %0, %1;" : "=r"(u) : "f"(x));
    return __uint_as_float(u);
}
__device__ __forceinline__ void ldsm_x4u(uint32_t* r, uint32_t addr) {
    asm volatile("ldmatrix.sync.aligned.m8n8.x4.shared.b16 {%0,%1,%2,%3}, [%4];"
        : "=r"(r[0]), "=r"(r[1]), "=r"(r[2]), "=r"(r[3]) : "r"(addr));
}
__device__ __forceinline__ void mma_tf32u(float* c, const uint32_t* a, uint32_t b0, uint32_t b1) {
    asm volatile(
        "mma.sync.aligned.m16n8k8.row.col.f32.tf32.tf32.f32 "
        "{%0,%1,%2,%3}, {%4,%5,%6,%7}, {%8,%9}, {%0,%1,%2,%3};"
        : "+f"(c[0]), "+f"(c[1]), "+f"(c[2]), "+f"(c[3])
        : "r"(a[0]), "r"(a[1]), "r"(a[2]), "r"(a[3]), "r"(b0), "r"(b1));
}

// ---------------- tf32 rounding pass ----------------
__global__ void __launch_bounds__(256)
round_tf32_kernel(const float* __restrict__ in, float* __restrict__ out, int n4)
{
    int i = blockIdx.x * 256 + threadIdx.x;
    if (i >= n4) return;
    float4 v = ((const float4*)in)[i];
    v.x = tf32r(v.x); v.y = tf32r(v.y); v.z = tf32r(v.z); v.w = tf32r(v.w);
    ((float4*)out)[i] = v;
}

// ---------------- W[K,N] fp32 -> Wt[N,K] tf32-rounded ----------------
__global__ void __launch_bounds__(256)
transpose_tf32_kernel(const float* __restrict__ W, float* __restrict__ Wt, int K, int N)
{
    __shared__ float t[32][33];
    const int k0 = blockIdx.y * 32, n0 = blockIdx.x * 32;
    const int tx = threadIdx.x & 31, ty = threadIdx.x >> 5;
#pragma unroll
    for (int i = 0; i < 32; i += 8)
        t[ty + i][tx] = W[(size_t)(k0 + ty + i) * N + n0 + tx];
    __syncthreads();
#pragma unroll
    for (int i = 0; i < 32; i += 8)
        Wt[(size_t)(n0 + ty + i) * K + k0 + tx] = tf32r(t[tx][ty + i]);
}

// ---------------- per-batch transpose: Vt[(b*E+c)][k] = V[(b*S+k)][c] ----------------
__global__ void __launch_bounds__(256)
vtrans_kernel(const float* __restrict__ V, float* __restrict__ Vt)
{
    __shared__ float t[32][33];
    const int b = blockIdx.z;
    const int k0 = blockIdx.x * 32, c0 = blockIdx.y * 32;
    const int tx = threadIdx.x & 31, ty = threadIdx.x >> 5;
#pragma unroll
    for (int i = 0; i < 32; i += 8)
        t[ty + i][tx] = V[(size_t)(b * Sq + k0 + ty + i) * Eq + c0 + tx];
    __syncthreads();
#pragma unroll
    for (int i = 0; i < 32; i += 8)
        Vt[(size_t)(b * Eq + c0 + ty + i) * Sq + k0 + tx] = t[tx][ty + i];
}

// ---------------- tf32 MMA GEMM, ldmatrix feed, one barrier per k-tile ----------------
#define KT 32
#define PAD 36
#define GSMEM (2 * 2 * 128 * PAD * 4)   // 73728 B

__global__ void __launch_bounds__(256)
gemm_tf32(const float* __restrict__ A, const float* __restrict__ Bt,
          const float* __restrict__ bias, float* __restrict__ C,
          int M, int K, int N, int relu, int round_out)
{
    extern __shared__ float sm[];
    const int tid = threadIdx.x;
    const int wid = tid >> 5, lane = tid & 31;
    const int wm = wid & 3, wn = wid >> 2;
    const int row0 = blockIdx.y * 128;
    const int col0 = blockIdx.x * 128;

    const uint32_t sbase = smem_u32(sm);
    const uint32_t MATB = 128 * PAD * 4;

    float acc[2][8][4];
#pragma unroll
    for (int i = 0; i < 2; i++)
#pragma unroll
        for (int j = 0; j < 8; j++)
#pragma unroll
            for (int k = 0; k < 4; k++) acc[i][j][k] = 0.f;

    const int NC = K / KT;

    auto load_tile = [&](int c, int buf) {
        const float* Ag = A  + (size_t)row0 * K + c * KT;
        const float* Bg = Bt + (size_t)col0 * K + c * KT;
        const uint32_t ab = sbase + (uint32_t)buf * 2 * MATB;
        const uint32_t bb = ab + MATB;
#pragma unroll
        for (int i = 0; i < 4; i++) {
            int id = tid + i * 256;
            int r = id >> 3, c4 = id & 7;
            uint32_t off = (uint32_t)(r * PAD + c4 * 4) * 4;
            cp_async16(ab + off, Ag + (size_t)r * K + c4 * 4);
            cp_async16(bb + off, Bg + (size_t)r * K + c4 * 4);
        }
        cp_commit();
    };

    load_tile(0, 0);

    // ldmatrix per-lane source rows/cols (fp32 units)
    const int arow = wm * 32 + (lane & 15);
    const int acol = (lane >> 4) << 2;
    const int brow = wn * 64 + ((lane >> 4) << 3) + (lane & 7);
    const int bcol = ((lane >> 3) & 1) << 2;

    for (int c = 0; c < NC; c++) {
        const int buf = c & 1;
        cp_wait<0>();            // exactly one group in flight
        __syncthreads();         // all warps done reading buf^1 from iter c-1
        if (c + 1 < NC) load_tile(c + 1, buf ^ 1);   // overlaps compute below

        const uint32_t au = sbase + (uint32_t)buf * 2 * MATB;
        const uint32_t bu = au + MATB;

#pragma unroll
        for (int ks = 0; ks < 4; ks++) {
            const int ck = ks * 8;
            uint32_t afr[2][4], bfr[4][4];
#pragma unroll
            for (int mi = 0; mi < 2; mi++)
                ldsm_x4u(afr[mi], au + (uint32_t)(((arow + mi * 16) * PAD) + ck + acol) * 4);
#pragma unroll
            for (int nip = 0; nip < 4; nip++)
                ldsm_x4u(bfr[nip], bu + (uint32_t)(((brow + nip * 16) * PAD) + ck + bcol) * 4);
#pragma unroll
            for (int mi = 0; mi < 2; mi++)
#pragma unroll
                for (int ni = 0; ni < 8; ni++)
                    mma_tf32u(acc[mi][ni], afr[mi],
                              bfr[ni >> 1][(ni & 1) * 2], bfr[ni >> 1][(ni & 1) * 2 + 1]);
        }
    }

    const int qr = lane >> 2;
    const int qc = (lane & 3) * 2;
#pragma unroll
    for (int mi = 0; mi < 2; mi++) {
#pragma unroll
        for (int ni = 0; ni < 8; ni++) {
            int col = col0 + wn * 64 + ni * 8 + qc;
            float b0 = bias[col], b1 = bias[col + 1];
            int r0 = row0 + wm * 32 + mi * 16 + qr;
            float v0 = acc[mi][ni][0] + b0;
            float v1 = acc[mi][ni][1] + b1;
            float v2 = acc[mi][ni][2] + b0;
            float v3 = acc[mi][ni][3] + b1;
            if (relu) {
                v0 = fmaxf(v0, 0.f); v1 = fmaxf(v1, 0.f);
                v2 = fmaxf(v2, 0.f); v3 = fmaxf(v3, 0.f);
            }
            if (round_out) {
                v0 = tf32r(v0); v1 = tf32r(v1);
                v2 = tf32r(v2); v3 = tf32r(v3);
            }
            *(float2*)(C + (size_t)r0 * N + col)       = make_float2(v0, v1);
            *(float2*)(C + (size_t)(r0 + 8) * N + col) = make_float2(v2, v3);
        }
    }
}

// ---------------- fused flash attention, ldmatrix feed ----------------
#define QT 64
#define KTL 128
#define QS 68
#define VS 132
#define FSMEM ((QT*QS + KTL*QS + 64*VS + QT*VS + 256) * 4)

__global__ void __launch_bounds__(256)
flash_kernel(const float* __restrict__ Qg, const float* __restrict__ Kg,
             const float* __restrict__ Vtg, const int* __restrict__ mask,
             float* __restrict__ ctx)
{
    extern __shared__ float sf[];
    float* Qs  = sf;                   // 64 x QS
    float* Ks  = Qs + QT * QS;         // 128 x QS
    float* Vts = Ks + KTL * QS;        // 64 x VS
    float* Ps  = Vts + 64 * VS;        // 64 x VS
    float* tmpM = Ps + QT * VS;        // 128
    float* tmpS = tmpM + 128;          // 128

    const int tid = threadIdx.x;
    const int wid = tid >> 5, lane = tid & 31;
    const int wm = wid & 3, wn = wid >> 2;
    const int qr = lane >> 2, qc = lane & 3;
    const int bh = blockIdx.y, b = bh >> 4, h = bh & 15;
    const int q0 = blockIdx.x * QT;

    const uint32_t qs_u = smem_u32(Qs), ks_u = smem_u32(Ks), vs_u = smem_u32(Vts);
    const uint32_t ps_u = smem_u32(Ps);

    // ldmatrix per-lane rows/cols
    const int arow = wm * 16 + (lane & 15);                    // A rows (Q / P)
    const int acol = (lane >> 4) << 2;                          // k-half
    const int brow = ((lane >> 4) << 3) + (lane & 7);           // B row within 16-block
    const int bcol = ((lane >> 3) & 1) << 2;

    // load Q tile (once)
#pragma unroll
    for (int i = 0; i < 4; i++) {
        int id = tid + i * 256;
        int r = id >> 4, ch = id & 15;
        cp_async16(qs_u + (uint32_t)(r * QS + ch * 4) * 4,
                   Qg + (size_t)(b * Sq + q0 + r) * Eq + h * 64 + ch * 4);
    }
    cp_commit();

    float m0 = -INFINITY, m1 = -INFINITY;
    float l0 = 0.f, l1 = 0.f;
    float acc_o[4][4] = {};

    const int rloc = wm * 16 + qr;

    for (int kt = 0; kt < Sq / KTL; kt++) {
        // load K tile and Vt tile
#pragma unroll
        for (int i = 0; i < 8; i++) {
            int id = tid + i * 256;
            int r = id >> 4, ch = id & 15;
            cp_async16(ks_u + (uint32_t)(r * QS + ch * 4) * 4,
                       Kg + (size_t)(b * Sq + kt * KTL + r) * Eq + h * 64 + ch * 4);
        }
#pragma unroll
        for (int i = 0; i < 8; i++) {
            int id = tid + i * 256;
            int r = id >> 5, ch = id & 31;
            cp_async16(vs_u + (uint32_t)(r * VS + ch * 4) * 4,
                       Vtg + (size_t)(b * Eq + h * 64 + r) * Sq + kt * KTL + ch * 4);
        }
        cp_commit();
        cp_wait<0>();
        __syncthreads();

        // S = Q @ K^T (ldmatrix feed)
        float acc_s[8][4];
#pragma unroll
        for (int ni = 0; ni < 8; ni++)
#pragma unroll
            for (int k = 0; k < 4; k++) acc_s[ni][k] = 0.f;
#pragma unroll
        for (int ks = 0; ks < 8; ks++) {
            const int ck = ks * 8;
            uint32_t afr[4];
            ldsm_x4u(afr, qs_u + (uint32_t)(arow * QS + ck + acol) * 4);
#pragma unroll
            for (int nip = 0; nip < 4; nip++) {
                uint32_t bfr[4];
                ldsm_x4u(bfr, ks_u + (uint32_t)((wn * 64 + nip * 16 + brow) * QS + ck + bcol) * 4);
                mma_tf32u(acc_s[nip * 2],     afr, bfr[0], bfr[1]);
                mma_tf32u(acc_s[nip * 2 + 1], afr, bfr[2], bfr[3]);
            }
        }

        // mask + rsqrt, row max
        float mr0 = -INFINITY, mr1 = -INFINITY;
#pragma unroll
        for (int ni = 0; ni < 8; ni++) {
            int colg = kt * KTL + wn * 64 + ni * 8 + qc * 2;
            int mk0 = mask[b * Sq + colg], mk1 = mask[b * Sq + colg + 1];
            float s0 = mk0 ? rsqrtf(acc_s[ni][0]) : -INFINITY;
            float s1 = mk1 ? rsqrtf(acc_s[ni][1]) : -INFINITY;
            float s2 = mk0 ? rsqrtf(acc_s[ni][2]) : -INFINITY;
            float s3 = mk1 ? rsqrtf(acc_s[ni][3]) : -INFINITY;
            acc_s[ni][0] = s0; acc_s[ni][1] = s1; acc_s[ni][2] = s2; acc_s[ni][3] = s3;
            mr0 = fmaxf(mr0, fmaxf(s0, s1));
            mr1 = fmaxf(mr1, fmaxf(s2, s3));
        }
#pragma unroll
        for (int o = 1; o < 4; o <<= 1) {
            mr0 = fmaxf(mr0, __shfl_xor_sync(0xffffffffu, mr0, o));
            mr1 = fmaxf(mr1, __shfl_xor_sync(0xffffffffu, mr1, o));
        }
        if (qc == 0) { tmpM[wn * 64 + rloc] = mr0; tmpM[wn * 64 + rloc + 8] = mr1; }
        __syncthreads();
        float mt0 = fmaxf(tmpM[rloc],     tmpM[64 + rloc]);
        float mt1 = fmaxf(tmpM[rloc + 8], tmpM[64 + rloc + 8]);
        float mn0 = fmaxf(m0, mt0), mn1 = fmaxf(m1, mt1);
        float mn0s = (mn0 == -INFINITY) ? 0.f : mn0;
        float mn1s = (mn1 == -INFINITY) ? 0.f : mn1;
        float sc0 = __expf(m0 - mn0s);
        float sc1 = __expf(m1 - mn1s);
        m0 = mn0; m1 = mn1;

        // exp, row sum, store P (tf32-rounded)
        float sr0 = 0.f, sr1 = 0.f;
#pragma unroll
        for (int ni = 0; ni < 8; ni++) {
            float p0 = __expf(acc_s[ni][0] - mn0s);
            float p1 = __expf(acc_s[ni][1] - mn0s);
            float p2 = __expf(acc_s[ni][2] - mn1s);
            float p3 = __expf(acc_s[ni][3] - mn1s);
            sr0 += p0 + p1; sr1 += p2 + p3;
            int colp = wn * 64 + ni * 8 + qc * 2;
            Ps[rloc * VS + colp]           = tf32r(p0);
            Ps[rloc * VS + colp + 1]       = tf32r(p1);
            Ps[(rloc + 8) * VS + colp]     = tf32r(p2);
            Ps[(rloc + 8) * VS + colp + 1] = tf32r(p3);
        }
#pragma unroll
        for (int o = 1; o < 4; o <<= 1) {
            sr0 += __shfl_xor_sync(0xffffffffu, sr0, o);
            sr1 += __shfl_xor_sync(0xffffffffu, sr1, o);
        }
        if (qc == 0) { tmpS[wn * 64 + rloc] = sr0; tmpS[wn * 64 + rloc + 8] = sr1; }
        __syncthreads();   // P + tmpS visible
        l0 = l0 * sc0 + tmpS[rloc]     + tmpS[64 + rloc];
        l1 = l1 * sc1 + tmpS[rloc + 8] + tmpS[64 + rloc + 8];

        // rescale O
#pragma unroll
        for (int ni = 0; ni < 4; ni++) {
            acc_o[ni][0] *= sc0; acc_o[ni][1] *= sc0;
            acc_o[ni][2] *= sc1; acc_o[ni][3] *= sc1;
        }

        // O += P @ V (ldmatrix feed)
#pragma unroll
        for (int ks = 0; ks < 16; ks++) {
            const int ck = ks * 8;
            uint32_t afr[4];
            ldsm_x4u(afr, ps_u + (uint32_t)(arow * VS + ck + acol) * 4);
#pragma unroll
            for (int nip = 0; nip < 2; nip++) {
                uint32_t bfr[4];
                ldsm_x4u(bfr, vs_u + (uint32_t)((wn * 32 + nip * 16 + brow) * VS + ck + bcol) * 4);
                mma_tf32u(acc_o[nip * 2],     afr, bfr[0], bfr[1]);
                mma_tf32u(acc_o[nip * 2 + 1], afr, bfr[2], bfr[3]);
            }
        }
        __syncthreads();   // before next tile overwrites Ks/Vts/Ps
    }

    // epilogue
    float inv0 = 1.f / l0, inv1 = 1.f / l1;
#pragma unroll
    for (int ni = 0; ni < 4; ni++) {
        int col = h * 64 + wn * 32 + ni * 8 + qc * 2;
        size_t r = (size_t)(b * Sq + q0 + rloc);
        *(float2*)(ctx + r * Eq + col) =
            make_float2(tf32r(acc_o[ni][0] * inv0), tf32r(acc_o[ni][1] * inv0));
        *(float2*)(ctx + (r + 8) * Eq + col) =
            make_float2(tf32r(acc_o[ni][2] * inv1), tf32r(acc_o[ni][3] * inv1));
    }
}

// ---------------- out = LayerNorm(A + R); optional tf32-rounded copy ----------------
__global__ void __launch_bounds__(256)
add_ln_kernel(const float* __restrict__ A, const float* __restrict__ R,
              const float* __restrict__ g, const float* __restrict__ be,
              float* __restrict__ out, float* __restrict__ out_r)
{
    const size_t row = blockIdx.x;
    const int tid = threadIdx.x;
    const int lane = tid & 31, warp = tid >> 5;
    __shared__ float red[8];
    const float* pa = A + row * Eq;
    const float* pr = R + row * Eq;

    float v[4];
    float s = 0.f;
#pragma unroll
    for (int i = 0; i < 4; i++) {
        v[i] = pa[tid + i * 256] + pr[tid + i * 256];
        s += v[i];
    }
#pragma unroll
    for (int o = 16; o; o >>= 1) s += __shfl_xor_sync(0xffffffffu, s, o);
    if (lane == 0) red[warp] = s;
    __syncthreads();
    if (tid == 0) {
        float t = 0.f;
#pragma unroll
        for (int i = 0; i < 8; i++) t += red[i];
        red[0] = t;
    }
    __syncthreads();
    const float mean = red[0] * (1.f / Eq);
    __syncthreads();

    float s2 = 0.f;
#pragma unroll
    for (int i = 0; i < 4; i++) {
        float d = v[i] - mean;
        s2 += d * d;
    }
#pragma unroll
    for (int o = 16; o; o >>= 1) s2 += __shfl_xor_sync(0xffffffffu, s2, o);
    if (lane == 0) red[warp] = s2;
    __syncthreads();
    if (tid == 0) {
        float t = 0.f;
#pragma unroll
        for (int i = 0; i < 8; i++) t += red[i];
        red[0] = t;
    }
    __syncthreads();
    const float inv = rsqrtf(red[0] * (1.f / Eq) + LN_EPS);

#pragma unroll
    for (int i = 0; i < 4; i++) {
        int c = tid + i * 256;
        float o = (v[i] - mean) * inv * g[c] + be[c];
        out[row * Eq + c] = o;
        if (out_r) out_r[row * Eq + c] = tf32r(o);
    }
}

// ---------------- host launch ----------------
extern "C" void kernel_launch(void* const* d_in, const int* in_sizes, int n_in,
                              void* d_out, int out_size)
{
    const float* value = (const float*)d_in[0];
    const float* key   = (const float*)d_in[1];
    const float* query = (const float*)d_in[2];
    const int*   mask  = (const int*)d_in[3];
    const float* Wv = (const float*)d_in[4];
    const float* bv = (const float*)d_in[5];
    const float* Wk = (const float*)d_in[6];
    const float* bk = (const float*)d_in[7];
    const float* Wq = (const float*)d_in[8];
    const float* bq = (const float*)d_in[9];
    const float* Wo = (const float*)d_in[10];
    const float* bo = (const float*)d_in[11];
    const float* W1 = (const float*)d_in[12];
    const float* b1 = (const float*)d_in[13];
    const float* W2 = (const float*)d_in[14];
    const float* b2 = (const float*)d_in[15];
    const float* g1  = (const float*)d_in[16];
    const float* be1 = (const float*)d_in[17];
    const float* g2  = (const float*)d_in[18];
    const float* be2 = (const float*)d_in[19];
    float* out = (float*)d_out;

    float *pV, *pK, *pQ, *pVt, *pCtx, *pAo, *pX, *pXr, *pH, *pFf;
    float *pVr, *pKr, *pQr;
    float *pWvt, *pWkt, *pWqt, *pWot, *pW1t, *pW2t;
    cudaGetSymbolAddress((void**)&pV,   g_V);
    cudaGetSymbolAddress((void**)&pK,   g_K);
    cudaGetSymbolAddress((void**)&pQ,   g_Q);
    cudaGetSymbolAddress((void**)&pVt,  g_Vt);
    cudaGetSymbolAddress((void**)&pCtx, g_ctx);
    cudaGetSymbolAddress((void**)&pAo,  g_ao);
    cudaGetSymbolAddress((void**)&pX,   g_x);
    cudaGetSymbolAddress((void**)&pXr,  g_xr);
    cudaGetSymbolAddress((void**)&pH,   g_h);
    cudaGetSymbolAddress((void**)&pFf,  g_ff);
    cudaGetSymbolAddress((void**)&pVr,  g_vr);
    cudaGetSymbolAddress((void**)&pKr,  g_kr);
    cudaGetSymbolAddress((void**)&pQr,  g_qr);
    cudaGetSymbolAddress((void**)&pWvt, g_Wvt);
    cudaGetSymbolAddress((void**)&pWkt, g_Wkt);
    cudaGetSymbolAddress((void**)&pWqt, g_Wqt);
    cudaGetSymbolAddress((void**)&pWot, g_Wot);
    cudaGetSymbolAddress((void**)&pW1t, g_W1t);
    cudaGetSymbolAddress((void**)&pW2t, g_W2t);

    cudaFuncSetAttribute(gemm_tf32, cudaFuncAttributeMaxDynamicSharedMemorySize, GSMEM);
    cudaFuncSetAttribute(flash_kernel, cudaFuncAttributeMaxDynamicSharedMemorySize, FSMEM);

    const int M = Bq * Sq;  // 4096
    dim3 blk(256);

    // weight transpose + tf32 rounding
    transpose_tf32_kernel<<<dim3(Eq / 32, Eq / 32), blk>>>(Wv, pWvt, Eq, Eq);
    transpose_tf32_kernel<<<dim3(Eq / 32, Eq / 32), blk>>>(Wk, pWkt, Eq, Eq);
    transpose_tf32_kernel<<<dim3(Eq / 32, Eq / 32), blk>>>(Wq, pWqt, Eq, Eq);
    transpose_tf32_kernel<<<dim3(Eq / 32, Eq / 32), blk>>>(Wo, pWot, Eq, Eq);
    transpose_tf32_kernel<<<dim3(FFq / 32, Eq / 32), blk>>>(W1, pW1t, Eq, FFq);
    transpose_tf32_kernel<<<dim3(Eq / 32, FFq / 32), blk>>>(W2, pW2t, FFq, Eq);

    // round activations feeding QKV GEMMs
    {
        int n4 = M * Eq / 4;
        round_tf32_kernel<<<(n4 + 255) / 256, 256>>>(value, pVr, n4);
        round_tf32_kernel<<<(n4 + 255) / 256, 256>>>(key,   pKr, n4);
        round_tf32_kernel<<<(n4 + 255) / 256, 256>>>(query, pQr, n4);
    }

    // QKV projections (tf32 MMA), outputs tf32-rounded for attention
    dim3 grid_e(Eq / 128, M / 128);
    gemm_tf32<<<grid_e, blk, GSMEM>>>(pVr, pWvt, bv, pV, M, Eq, Eq, 0, 1);
    gemm_tf32<<<grid_e, blk, GSMEM>>>(pKr, pWkt, bk, pK, M, Eq, Eq, 0, 1);
    gemm_tf32<<<grid_e, blk, GSMEM>>>(pQr, pWqt, bq, pQ, M, Eq, Eq, 0, 1);

    // V transpose per batch
    vtrans_kernel<<<dim3(Sq / 32, Eq / 32, Bq), blk>>>(pV, pVt);

    // fused flash attention -> ctx (tf32-rounded)
    flash_kernel<<<dim3(Sq / QT, Bq * Hh), blk, FSMEM>>>(pQ, pK, pVt, mask, pCtx);

    // output projection
    gemm_tf32<<<grid_e, blk, GSMEM>>>(pCtx, pWot, bo, pAo, M, Eq, Eq, 0, 0);

    // x = LN(attn_out + query); tf32-rounded copy for FFN1
    add_ln_kernel<<<M, blk>>>(pAo, query, g1, be1, pX, pXr);

    // FFN1
    dim3 grid_ff1(FFq / 128, M / 128);
    gemm_tf32<<<grid_ff1, blk, GSMEM>>>(pXr, pW1t, b1, pH, M, Eq, FFq, 1, 1);

    // FFN2
    dim3 grid_ff2(Eq / 128, M / 128);
    gemm_tf32<<<grid_ff2, blk, GSMEM>>>(pH, pW2t, b2, pFf, M, FFq, Eq, 0, 0);

    // out = LN(ff + x)
    add_ln_kernel<<<M, blk>>>(pFf, pX, g2, be2, out, nullptr);
}

// round 11
// speedup vs baseline: 1.4528x; 1.0745x over previous
#include <cuda_runtime.h>
#include <math.h>
#include <stdint.h>

// ---------------- problem dims ----------------
#define Bq 4
#define Sq 1024
#define Eq 1024
#define Hh 16
#define Dd 64
#define FFq 4096
#define LN_EPS 1e-5f

// ---------------- scratch (device globals) ----------------
__device__ float g_V[Bq * Sq * Eq];
__device__ float g_K[Bq * Sq * Eq];
__device__ float g_Q[Bq * Sq * Eq];
__device__ float g_Vt[Bq * Sq * Eq];
__device__ float g_ctx[Bq * Sq * Eq];
__device__ float g_ao[Bq * Sq * Eq];
__device__ float g_x[Bq * Sq * Eq];
__device__ float g_xr[Bq * Sq * Eq];
__device__ float g_h[(size_t)Bq * Sq * FFq];
__device__ float g_ff[Bq * Sq * Eq];
__device__ float g_vr[Bq * Sq * Eq];
__device__ float g_kr[Bq * Sq * Eq];
__device__ float g_qr[Bq * Sq * Eq];
__device__ float g_Wvt[Eq * Eq];
__device__ float g_Wkt[Eq * Eq];
__device__ float g_Wqt[Eq * Eq];
__device__ float g_Wot[Eq * Eq];
__device__ float g_W1t[(size_t)Eq * FFq];
__device__ float g_W2t[(size_t)Eq * FFq];

// ---------------- PTX helpers ----------------
__device__ __forceinline__ uint32_t smem_u32(const void* p) {
    uint32_t a;
    asm("{ .reg .u64 t; cvta.to.shared.u64 t, %1; cvt.u32.u64 %0, t; }" : "=r"(a) : "l"(p));
    return a;
}
__device__ __forceinline__ void cp_async16(uint32_t dst, const void* src) {
    asm volatile("cp.async.ca.shared.global [%0], [%1], 16;" :: "r"(dst), "l"(src));
}
__device__ __forceinline__ void cp_commit() { asm volatile("cp.async.commit_group;"); }
template <int N>
__device__ __forceinline__ void cp_wait() { asm volatile("cp.async.wait_group %0;" :: "n"(N)); }

__device__ __forceinline__ float tf32r(float x) {
    uint32_t u;
    asm("cvt.rna.tf32.f32 %0, %1;" : "=r"(u) : "f"(x));
    return __uint_as_float(u);
}
__device__ __forceinline__ void ldsm_x4u(uint32_t* r, uint32_t addr) {
    asm volatile("ldmatrix.sync.aligned.m8n8.x4.shared.b16 {%0,%1,%2,%3}, [%4];"
        : "=r"(r[0]), "=r"(r[1]), "=r"(r[2]), "=r"(r[3]) : "r"(addr));
}
__device__ __forceinline__ void mma_tf32u(float* c, const uint32_t* a, uint32_t b0, uint32_t b1) {
    asm volatile(
        "mma.sync.aligned.m16n8k8.row.col.f32.tf32.tf32.f32 "
        "{%0,%1,%2,%3}, {%4,%5,%6,%7}, {%8,%9}, {%0,%1,%2,%3};"
        : "+f"(c[0]), "+f"(c[1]), "+f"(c[2]), "+f"(c[3])
        : "r"(a[0]), "r"(a[1]), "r"(a[2]), "r"(a[3]), "r"(b0), "r"(b1));
}

// ---------------- tf32 rounding pass ----------------
__global__ void __launch_bounds__(256)
round_tf32_kernel(const float* __restrict__ in, float* __restrict__ out, int n4)
{
    int i = blockIdx.x * 256 + threadIdx.x;
    if (i >= n4) return;
    float4 v = ((const float4*)in)[i];
    v.x = tf32r(v.x); v.y = tf32r(v.y); v.z = tf32r(v.z); v.w = tf32r(v.w);
    ((float4*)out)[i] = v;
}

// ---------------- W[K,N] fp32 -> Wt[N,K] tf32-rounded ----------------
__global__ void __launch_bounds__(256)
transpose_tf32_kernel(const float* __restrict__ W, float* __restrict__ Wt, int K, int N)
{
    __shared__ float t[32][33];
    const int k0 = blockIdx.y * 32, n0 = blockIdx.x * 32;
    const int tx = threadIdx.x & 31, ty = threadIdx.x >> 5;
#pragma unroll
    for (int i = 0; i < 32; i += 8)
        t[ty + i][tx] = W[(size_t)(k0 + ty + i) * N + n0 + tx];
    __syncthreads();
#pragma unroll
    for (int i = 0; i < 32; i += 8)
        Wt[(size_t)(n0 + ty + i) * K + k0 + tx] = tf32r(t[tx][ty + i]);
}

// ---------------- per-batch transpose: Vt[(b*E+c)][k] = V[(b*S+k)][c] ----------------
__global__ void __launch_bounds__(256)
vtrans_kernel(const float* __restrict__ V, float* __restrict__ Vt)
{
    __shared__ float t[32][33];
    const int b = blockIdx.z;
    const int k0 = blockIdx.x * 32, c0 = blockIdx.y * 32;
    const int tx = threadIdx.x & 31, ty = threadIdx.x >> 5;
#pragma unroll
    for (int i = 0; i < 32; i += 8)
        t[ty + i][tx] = V[(size_t)(b * Sq + k0 + ty + i) * Eq + c0 + tx];
    __syncthreads();
#pragma unroll
    for (int i = 0; i < 32; i += 8)
        Vt[(size_t)(b * Eq + c0 + ty + i) * Sq + k0 + tx] = t[tx][ty + i];
}

// ---------------- tf32 MMA GEMM (R10 version, known-good) ----------------
#define KT 32
#define PAD 36
#define GSMEM (2 * 2 * 128 * PAD * 4)   // 73728 B

__global__ void __launch_bounds__(256)
gemm_tf32(const float* __restrict__ A, const float* __restrict__ Bt,
          const float* __restrict__ bias, float* __restrict__ C,
          int M, int K, int N, int relu, int round_out)
{
    extern __shared__ float sm[];
    const int tid = threadIdx.x;
    const int wid = tid >> 5, lane = tid & 31;
    const int wm = wid & 3, wn = wid >> 2;
    const int row0 = blockIdx.y * 128;
    const int col0 = blockIdx.x * 128;

    const uint32_t sbase = smem_u32(sm);
    const uint32_t MATB = 128 * PAD * 4;

    float acc[2][8][4];
#pragma unroll
    for (int i = 0; i < 2; i++)
#pragma unroll
        for (int j = 0; j < 8; j++)
#pragma unroll
            for (int k = 0; k < 4; k++) acc[i][j][k] = 0.f;

    const int NC = K / KT;

    auto load_tile = [&](int c, int buf) {
        const float* Ag = A  + (size_t)row0 * K + c * KT;
        const float* Bg = Bt + (size_t)col0 * K + c * KT;
        const uint32_t ab = sbase + (uint32_t)buf * 2 * MATB;
        const uint32_t bb = ab + MATB;
#pragma unroll
        for (int i = 0; i < 4; i++) {
            int id = tid + i * 256;
            int r = id >> 3, c4 = id & 7;
            uint32_t off = (uint32_t)(r * PAD + c4 * 4) * 4;
            cp_async16(ab + off, Ag + (size_t)r * K + c4 * 4);
            cp_async16(bb + off, Bg + (size_t)r * K + c4 * 4);
        }
        cp_commit();
    };

    load_tile(0, 0);

    // ldmatrix per-lane source rows/cols (fp32 units)
    const int arow = wm * 32 + (lane & 15);
    const int acol = (lane >> 4) << 2;
    const int brow = wn * 64 + ((lane >> 4) << 3) + (lane & 7);
    const int bcol = ((lane >> 3) & 1) << 2;

    for (int c = 0; c < NC; c++) {
        const int buf = c & 1;
        cp_wait<0>();            // exactly one group in flight
        __syncthreads();         // all warps done reading buf^1 from iter c-1
        if (c + 1 < NC) load_tile(c + 1, buf ^ 1);   // overlaps compute below

        const uint32_t au = sbase + (uint32_t)buf * 2 * MATB;
        const uint32_t bu = au + MATB;

#pragma unroll
        for (int ks = 0; ks < 4; ks++) {
            const int ck = ks * 8;
            uint32_t afr[2][4], bfr[4][4];
#pragma unroll
            for (int mi = 0; mi < 2; mi++)
                ldsm_x4u(afr[mi], au + (uint32_t)(((arow + mi * 16) * PAD) + ck + acol) * 4);
#pragma unroll
            for (int nip = 0; nip < 4; nip++)
                ldsm_x4u(bfr[nip], bu + (uint32_t)(((brow + nip * 16) * PAD) + ck + bcol) * 4);
#pragma unroll
            for (int mi = 0; mi < 2; mi++)
#pragma unroll
                for (int ni = 0; ni < 8; ni++)
                    mma_tf32u(acc[mi][ni], afr[mi],
                              bfr[ni >> 1][(ni & 1) * 2], bfr[ni >> 1][(ni & 1) * 2 + 1]);
        }
    }

    const int qr = lane >> 2;
    const int qc = (lane & 3) * 2;
#pragma unroll
    for (int mi = 0; mi < 2; mi++) {
#pragma unroll
        for (int ni = 0; ni < 8; ni++) {
            int col = col0 + wn * 64 + ni * 8 + qc;
            float b0 = bias[col], b1 = bias[col + 1];
            int r0 = row0 + wm * 32 + mi * 16 + qr;
            float v0 = acc[mi][ni][0] + b0;
            float v1 = acc[mi][ni][1] + b1;
            float v2 = acc[mi][ni][2] + b0;
            float v3 = acc[mi][ni][3] + b1;
            if (relu) {
                v0 = fmaxf(v0, 0.f); v1 = fmaxf(v1, 0.f);
                v2 = fmaxf(v2, 0.f); v3 = fmaxf(v3, 0.f);
            }
            if (round_out) {
                v0 = tf32r(v0); v1 = tf32r(v1);
                v2 = tf32r(v2); v3 = tf32r(v3);
            }
            *(float2*)(C + (size_t)r0 * N + col)       = make_float2(v0, v1);
            *(float2*)(C + (size_t)(r0 + 8) * N + col) = make_float2(v2, v3);
        }
    }
}

// ---------------- fused flash attention, P aliased onto K tile -> 2 CTAs/SM ----------------
// smem: Q(64xQS) + K∪P(128xQS) + Vt(64xVS) + tmp(256) = 87,040 B
// Safety: tmpM barrier separates all K reads (S-loop) from P writes;
// tmpS barrier separates P writes from P reads (O-loop);
// trailing barrier separates P reads from next tile's K cp.async.
#define QT 64
#define KTL 128
#define QS 68
#define VS 132
#define FSMEM ((QT*QS + KTL*QS + 64*VS + 256) * 4)   // 87040 B

__global__ void __launch_bounds__(256, 2)
flash_kernel(const float* __restrict__ Qg, const float* __restrict__ Kg,
             const float* __restrict__ Vtg, const int* __restrict__ mask,
             float* __restrict__ ctx)
{
    extern __shared__ float sf[];
    float* Qs  = sf;                   // 64 x QS
    float* Ks  = Qs + QT * QS;         // 128 x QS  (K tile; P tile aliases this region)
    float* Vts = Ks + KTL * QS;        // 64 x VS
    float* Ps  = Ks;                   // alias: P (64 x VS = 8448 floats <= 8704)
    float* tmpM = Vts + 64 * VS;       // 128
    float* tmpS = tmpM + 128;          // 128

    const int tid = threadIdx.x;
    const int wid = tid >> 5, lane = tid & 31;
    const int wm = wid & 3, wn = wid >> 2;
    const int qr = lane >> 2, qc = lane & 3;
    const int bh = blockIdx.y, b = bh >> 4, h = bh & 15;
    const int q0 = blockIdx.x * QT;

    const uint32_t qs_u = smem_u32(Qs), ks_u = smem_u32(Ks), vs_u = smem_u32(Vts);
    const uint32_t ps_u = ks_u;

    // ldmatrix per-lane rows/cols
    const int arow = wm * 16 + (lane & 15);                    // A rows (Q / P)
    const int acol = (lane >> 4) << 2;                          // k-half
    const int brow = ((lane >> 4) << 3) + (lane & 7);           // B row within 16-block
    const int bcol = ((lane >> 3) & 1) << 2;

    // load Q tile (once)
#pragma unroll
    for (int i = 0; i < 4; i++) {
        int id = tid + i * 256;
        int r = id >> 4, ch = id & 15;
        cp_async16(qs_u + (uint32_t)(r * QS + ch * 4) * 4,
                   Qg + (size_t)(b * Sq + q0 + r) * Eq + h * 64 + ch * 4);
    }
    cp_commit();

    float m0 = -INFINITY, m1 = -INFINITY;
    float l0 = 0.f, l1 = 0.f;
    float acc_o[4][4] = {};

    const int rloc = wm * 16 + qr;

    for (int kt = 0; kt < Sq / KTL; kt++) {
        // load K tile and Vt tile
#pragma unroll
        for (int i = 0; i < 8; i++) {
            int id = tid + i * 256;
            int r = id >> 4, ch = id & 15;
            cp_async16(ks_u + (uint32_t)(r * QS + ch * 4) * 4,
                       Kg + (size_t)(b * Sq + kt * KTL + r) * Eq + h * 64 + ch * 4);
        }
#pragma unroll
        for (int i = 0; i < 8; i++) {
            int id = tid + i * 256;
            int r = id >> 5, ch = id & 31;
            cp_async16(vs_u + (uint32_t)(r * VS + ch * 4) * 4,
                       Vtg + (size_t)(b * Eq + h * 64 + r) * Sq + kt * KTL + ch * 4);
        }
        cp_commit();
        cp_wait<0>();
        __syncthreads();

        // S = Q @ K^T (ldmatrix feed)
        float acc_s[8][4];
#pragma unroll
        for (int ni = 0; ni < 8; ni++)
#pragma unroll
            for (int k = 0; k < 4; k++) acc_s[ni][k] = 0.f;
#pragma unroll
        for (int ks = 0; ks < 8; ks++) {
            const int ck = ks * 8;
            uint32_t afr[4];
            ldsm_x4u(afr, qs_u + (uint32_t)(arow * QS + ck + acol) * 4);
#pragma unroll
            for (int nip = 0; nip < 4; nip++) {
                uint32_t bfr[4];
                ldsm_x4u(bfr, ks_u + (uint32_t)((wn * 64 + nip * 16 + brow) * QS + ck + bcol) * 4);
                mma_tf32u(acc_s[nip * 2],     afr, bfr[0], bfr[1]);
                mma_tf32u(acc_s[nip * 2 + 1], afr, bfr[2], bfr[3]);
            }
        }

        // mask + rsqrt, row max
        float mr0 = -INFINITY, mr1 = -INFINITY;
#pragma unroll
        for (int ni = 0; ni < 8; ni++) {
            int colg = kt * KTL + wn * 64 + ni * 8 + qc * 2;
            int mk0 = mask[b * Sq + colg], mk1 = mask[b * Sq + colg + 1];
            float s0 = mk0 ? rsqrtf(acc_s[ni][0]) : -INFINITY;
            float s1 = mk1 ? rsqrtf(acc_s[ni][1]) : -INFINITY;
            float s2 = mk0 ? rsqrtf(acc_s[ni][2]) : -INFINITY;
            float s3 = mk1 ? rsqrtf(acc_s[ni][3]) : -INFINITY;
            acc_s[ni][0] = s0; acc_s[ni][1] = s1; acc_s[ni][2] = s2; acc_s[ni][3] = s3;
            mr0 = fmaxf(mr0, fmaxf(s0, s1));
            mr1 = fmaxf(mr1, fmaxf(s2, s3));
        }
#pragma unroll
        for (int o = 1; o < 4; o <<= 1) {
            mr0 = fmaxf(mr0, __shfl_xor_sync(0xffffffffu, mr0, o));
            mr1 = fmaxf(mr1, __shfl_xor_sync(0xffffffffu, mr1, o));
        }
        if (qc == 0) { tmpM[wn * 64 + rloc] = mr0; tmpM[wn * 64 + rloc + 8] = mr1; }
        __syncthreads();   // also: last K read (S-loop) is before this barrier
        float mt0 = fmaxf(tmpM[rloc],     tmpM[64 + rloc]);
        float mt1 = fmaxf(tmpM[rloc + 8], tmpM[64 + rloc + 8]);
        float mn0 = fmaxf(m0, mt0), mn1 = fmaxf(m1, mt1);
        float mn0s = (mn0 == -INFINITY) ? 0.f : mn0;
        float mn1s = (mn1 == -INFINITY) ? 0.f : mn1;
        float sc0 = __expf(m0 - mn0s);
        float sc1 = __expf(m1 - mn1s);
        m0 = mn0; m1 = mn1;

        // exp, row sum, store P (tf32-rounded) into the dead K region
        float sr0 = 0.f, sr1 = 0.f;
#pragma unroll
        for (int ni = 0; ni < 8; ni++) {
            float p0 = __expf(acc_s[ni][0] - mn0s);
            float p1 = __expf(acc_s[ni][1] - mn0s);
            float p2 = __expf(acc_s[ni][2] - mn1s);
            float p3 = __expf(acc_s[ni][3] - mn1s);
            sr0 += p0 + p1; sr1 += p2 + p3;
            int colp = wn * 64 + ni * 8 + qc * 2;
            Ps[rloc * VS + colp]           = tf32r(p0);
            Ps[rloc * VS + colp + 1]       = tf32r(p1);
            Ps[(rloc + 8) * VS + colp]     = tf32r(p2);
            Ps[(rloc + 8) * VS + colp + 1] = tf32r(p3);
        }
#pragma unroll
        for (int o = 1; o < 4; o <<= 1) {
            sr0 += __shfl_xor_sync(0xffffffffu, sr0, o);
            sr1 += __shfl_xor_sync(0xffffffffu, sr1, o);
        }
        if (qc == 0) { tmpS[wn * 64 + rloc] = sr0; tmpS[wn * 64 + rloc + 8] = sr1; }
        __syncthreads();   // P + tmpS visible
        l0 = l0 * sc0 + tmpS[rloc]     + tmpS[64 + rloc];
        l1 = l1 * sc1 + tmpS[rloc + 8] + tmpS[64 + rloc + 8];

        // rescale O
#pragma unroll
        for (int ni = 0; ni < 4; ni++) {
            acc_o[ni][0] *= sc0; acc_o[ni][1] *= sc0;
            acc_o[ni][2] *= sc1; acc_o[ni][3] *= sc1;
        }

        // O += P @ V (ldmatrix feed)
#pragma unroll
        for (int ks = 0; ks < 16; ks++) {
            const int ck = ks * 8;
            uint32_t afr[4];
            ldsm_x4u(afr, ps_u + (uint32_t)(arow * VS + ck + acol) * 4);
#pragma unroll
            for (int nip = 0; nip < 2; nip++) {
                uint32_t bfr[4];
                ldsm_x4u(bfr, vs_u + (uint32_t)((wn * 32 + nip * 16 + brow) * VS + ck + bcol) * 4);
                mma_tf32u(acc_o[nip * 2],     afr, bfr[0], bfr[1]);
                mma_tf32u(acc_o[nip * 2 + 1], afr, bfr[2], bfr[3]);
            }
        }
        __syncthreads();   // P reads done before next tile's K load overwrites
    }

    // epilogue
    float inv0 = 1.f / l0, inv1 = 1.f / l1;
#pragma unroll
    for (int ni = 0; ni < 4; ni++) {
        int col = h * 64 + wn * 32 + ni * 8 + qc * 2;
        size_t r = (size_t)(b * Sq + q0 + rloc);
        *(float2*)(ctx + r * Eq + col) =
            make_float2(tf32r(acc_o[ni][0] * inv0), tf32r(acc_o[ni][1] * inv0));
        *(float2*)(ctx + (r + 8) * Eq + col) =
            make_float2(tf32r(acc_o[ni][2] * inv1), tf32r(acc_o[ni][3] * inv1));
    }
}

// ---------------- out = LayerNorm(A + R); optional tf32-rounded copy ----------------
__global__ void __launch_bounds__(256)
add_ln_kernel(const float* __restrict__ A, const float* __restrict__ R,
              const float* __restrict__ g, const float* __restrict__ be,
              float* __restrict__ out, float* __restrict__ out_r)
{
    const size_t row = blockIdx.x;
    const int tid = threadIdx.x;
    const int lane = tid & 31, warp = tid >> 5;
    __shared__ float red[8];
    const float* pa = A + row * Eq;
    const float* pr = R + row * Eq;

    float v[4];
    float s = 0.f;
#pragma unroll
    for (int i = 0; i < 4; i++) {
        v[i] = pa[tid + i * 256] + pr[tid + i * 256];
        s += v[i];
    }
#pragma unroll
    for (int o = 16; o; o >>= 1) s += __shfl_xor_sync(0xffffffffu, s, o);
    if (lane == 0) red[warp] = s;
    __syncthreads();
    if (tid == 0) {
        float t = 0.f;
#pragma unroll
        for (int i = 0; i < 8; i++) t += red[i];
        red[0] = t;
    }
    __syncthreads();
    const float mean = red[0] * (1.f / Eq);
    __syncthreads();

    float s2 = 0.f;
#pragma unroll
    for (int i = 0; i < 4; i++) {
        float d = v[i] - mean;
        s2 += d * d;
    }
#pragma unroll
    for (int o = 16; o; o >>= 1) s2 += __shfl_xor_sync(0xffffffffu, s2, o);
    if (lane == 0) red[warp] = s2;
    __syncthreads();
    if (tid == 0) {
        float t = 0.f;
#pragma unroll
        for (int i = 0; i < 8; i++) t += red[i];
        red[0] = t;
    }
    __syncthreads();
    const float inv = rsqrtf(red[0] * (1.f / Eq) + LN_EPS);

#pragma unroll
    for (int i = 0; i < 4; i++) {
        int c = tid + i * 256;
        float o = (v[i] - mean) * inv * g[c] + be[c];
        out[row * Eq + c] = o;
        if (out_r) out_r[row * Eq + c] = tf32r(o);
    }
}

// ---------------- host launch ----------------
extern "C" void kernel_launch(void* const* d_in, const int* in_sizes, int n_in,
                              void* d_out, int out_size)
{
    const float* value = (const float*)d_in[0];
    const float* key   = (const float*)d_in[1];
    const float* query = (const float*)d_in[2];
    const int*   mask  = (const int*)d_in[3];
    const float* Wv = (const float*)d_in[4];
    const float* bv = (const float*)d_in[5];
    const float* Wk = (const float*)d_in[6];
    const float* bk = (const float*)d_in[7];
    const float* Wq = (const float*)d_in[8];
    const float* bq = (const float*)d_in[9];
    const float* Wo = (const float*)d_in[10];
    const float* bo = (const float*)d_in[11];
    const float* W1 = (const float*)d_in[12];
    const float* b1 = (const float*)d_in[13];
    const float* W2 = (const float*)d_in[14];
    const float* b2 = (const float*)d_in[15];
    const float* g1  = (const float*)d_in[16];
    const float* be1 = (const float*)d_in[17];
    const float* g2  = (const float*)d_in[18];
    const float* be2 = (const float*)d_in[19];
    float* out = (float*)d_out;

    float *pV, *pK, *pQ, *pVt, *pCtx, *pAo, *pX, *pXr, *pH, *pFf;
    float *pVr, *pKr, *pQr;
    float *pWvt, *pWkt, *pWqt, *pWot, *pW1t, *pW2t;
    cudaGetSymbolAddress((void**)&pV,   g_V);
    cudaGetSymbolAddress((void**)&pK,   g_K);
    cudaGetSymbolAddress((void**)&pQ,   g_Q);
    cudaGetSymbolAddress((void**)&pVt,  g_Vt);
    cudaGetSymbolAddress((void**)&pCtx, g_ctx);
    cudaGetSymbolAddress((void**)&pAo,  g_ao);
    cudaGetSymbolAddress((void**)&pX,   g_x);
    cudaGetSymbolAddress((void**)&pXr,  g_xr);
    cudaGetSymbolAddress((void**)&pH,   g_h);
    cudaGetSymbolAddress((void**)&pFf,  g_ff);
    cudaGetSymbolAddress((void**)&pVr,  g_vr);
    cudaGetSymbolAddress((void**)&pKr,  g_kr);
    cudaGetSymbolAddress((void**)&pQr,  g_qr);
    cudaGetSymbolAddress((void**)&pWvt, g_Wvt);
    cudaGetSymbolAddress((void**)&pWkt, g_Wkt);
    cudaGetSymbolAddress((void**)&pWqt, g_Wqt);
    cudaGetSymbolAddress((void**)&pWot, g_Wot);
    cudaGetSymbolAddress((void**)&pW1t, g_W1t);
    cudaGetSymbolAddress((void**)&pW2t, g_W2t);

    cudaFuncSetAttribute(gemm_tf32, cudaFuncAttributeMaxDynamicSharedMemorySize, GSMEM);
    cudaFuncSetAttribute(flash_kernel, cudaFuncAttributeMaxDynamicSharedMemorySize, FSMEM);

    const int M = Bq * Sq;  // 4096
    dim3 blk(256);

    // weight transpose + tf32 rounding
    transpose_tf32_kernel<<<dim3(Eq / 32, Eq / 32), blk>>>(Wv, pWvt, Eq, Eq);
    transpose_tf32_kernel<<<dim3(Eq / 32, Eq / 32), blk>>>(Wk, pWkt, Eq, Eq);
    transpose_tf32_kernel<<<dim3(Eq / 32, Eq / 32), blk>>>(Wq, pWqt, Eq, Eq);
    transpose_tf32_kernel<<<dim3(Eq / 32, Eq / 32), blk>>>(Wo, pWot, Eq, Eq);
    transpose_tf32_kernel<<<dim3(FFq / 32, Eq / 32), blk>>>(W1, pW1t, Eq, FFq);
    transpose_tf32_kernel<<<dim3(Eq / 32, FFq / 32), blk>>>(W2, pW2t, FFq, Eq);

    // round activations feeding QKV GEMMs
    {
        int n4 = M * Eq / 4;
        round_tf32_kernel<<<(n4 + 255) / 256, 256>>>(value, pVr, n4);
        round_tf32_kernel<<<(n4 + 255) / 256, 256>>>(key,   pKr, n4);
        round_tf32_kernel<<<(n4 + 255) / 256, 256>>>(query, pQr, n4);
    }

    // QKV projections (tf32 MMA), outputs tf32-rounded for attention
    dim3 grid_e(Eq / 128, M / 128);
    gemm_tf32<<<grid_e, blk, GSMEM>>>(pVr, pWvt, bv, pV, M, Eq, Eq, 0, 1);
    gemm_tf32<<<grid_e, blk, GSMEM>>>(pKr, pWkt, bk, pK, M, Eq, Eq, 0, 1);
    gemm_tf32<<<grid_e, blk, GSMEM>>>(pQr, pWqt, bq, pQ, M, Eq, Eq, 0, 1);

    // V transpose per batch
    vtrans_kernel<<<dim3(Sq / 32, Eq / 32, Bq), blk>>>(pV, pVt);

    // fused flash attention -> ctx (tf32-rounded)
    flash_kernel<<<dim3(Sq / QT, Bq * Hh), blk, FSMEM>>>(pQ, pK, pVt, mask, pCtx);

    // output projection
    gemm_tf32<<<grid_e, blk, GSMEM>>>(pCtx, pWot, bo, pAo, M, Eq, Eq, 0, 0);

    // x = LN(attn_out + query); tf32-rounded copy for FFN1
    add_ln_kernel<<<M, blk>>>(pAo, query, g1, be1, pX, pXr);

    // FFN1
    dim3 grid_ff1(FFq / 128, M / 128);
    gemm_tf32<<<grid_ff1, blk, GSMEM>>>(pXr, pW1t, b1, pH, M, Eq, FFq, 1, 1);

    // FFN2
    dim3 grid_ff2(Eq / 128, M / 128);
    gemm_tf32<<<grid_ff2, blk, GSMEM>>>(pH, pW2t, b2, pFf, M, FFq, Eq, 0, 0);

    // out = LN(ff + x)
    add_ln_kernel<<<M, blk>>>(pFf, pX, g2, be2, out, nullptr);
}